// round 14
// baseline (speedup 1.0000x reference)
#include <cuda_runtime.h>
#include <cuda_fp16.h>
#include <cstdint>
#include <math.h>

#define BB 16
#define C  128
#define F  128
#define HH 128
#define WW 128
#define KHH 31
#define KWW 31
#define OH 98
#define OW 98
#define NF 65          // rfft bins along W
#define NBIN (HH*NF)   // 8320 ; bin = k*128 + h  (k-major)
#define BC (BB*C)      // 2048
#define FC (F*C)       // 16384

// -------- scratch (device globals; no allocation allowed) --------
__device__ float2  g_xf [(size_t)BC  * NBIN];   // [b*C+c][bin]; K4 overwrites in place with of^T [b*F+f][bin]
__device__ __half2 g_kfn[(size_t)FC  * NBIN];   // [c*F+f][bin]  (plain fft, fp16)

// ---------------- helpers ----------------
__device__ __forceinline__ int swz(int w) { return w ^ ((w >> 4) & 7); }
// row-aware swizzle for k_fft_k buffers
__device__ __forceinline__ int swzc(int r, int w) {
    int v = w ^ ((r & 3) << 3);
    return v ^ ((v >> 4) & 7);
}
__device__ __forceinline__ float2 cadd(float2 a, float2 b){return make_float2(a.x+b.x, a.y+b.y);}
__device__ __forceinline__ float2 csub(float2 a, float2 b){return make_float2(a.x-b.x, a.y-b.y);}
__device__ __forceinline__ float2 cmul(float2 a, float2 b){return make_float2(a.x*b.x-a.y*b.y, a.x*b.y+a.y*b.x);}
__device__ __forceinline__ float2 cmulni(float2 a){return make_float2(a.y, -a.x);}  // a * (-i)

__device__ __forceinline__ void make_twiddles(float2* tw, int tid) {
    if (tid < 128) {
        float s, c;
        sincosf(-6.283185307179586f * (float)tid / 128.0f, &s, &c);
        tw[tid] = make_float2(c, s);
    }
}

__device__ __forceinline__ uint32_t smem_u32(const void* p) {
    uint32_t a;
    asm("{ .reg .u64 t; cvta.to.shared.u64 t, %1; cvt.u32.u64 %0, t; }" : "=r"(a) : "l"(p));
    return a;
}
__device__ __forceinline__ void cp8(uint32_t dst, const void* src) {
    asm volatile("cp.async.ca.shared.global [%0], [%1], 8;" :: "r"(dst), "l"(src));
}

// DFT8 natural order: c[k] = sum_j a[j] W8^{jk}
__device__ __forceinline__ void dft8(const float2* a, float2* c) {
    float2 t0 = cadd(a[0], a[4]), t1 = csub(a[0], a[4]);
    float2 t2 = cadd(a[2], a[6]), t3 = csub(a[2], a[6]);
    float2 m3 = cmulni(t3);
    float2 E0 = cadd(t0, t2), E2 = csub(t0, t2);
    float2 E1 = cadd(t1, m3), E3 = csub(t1, m3);
    t0 = cadd(a[1], a[5]); t1 = csub(a[1], a[5]);
    t2 = cadd(a[3], a[7]); t3 = csub(a[3], a[7]);
    m3 = cmulni(t3);
    float2 O0 = cadd(t0, t2), O2 = csub(t0, t2);
    float2 O1 = cadd(t1, m3), O3 = csub(t1, m3);
    const float s = 0.70710678118654752f;
    float2 w1o = make_float2(s * (O1.x + O1.y), s * (O1.y - O1.x));
    float2 w2o = cmulni(O2);
    float2 w3o = make_float2(s * (O3.y - O3.x), s * (-O3.x - O3.y));
    c[0] = cadd(E0, O0);  c[4] = csub(E0, O0);
    c[1] = cadd(E1, w1o); c[5] = csub(E1, w1o);
    c[2] = cadd(E2, w2o); c[6] = csub(E2, w2o);
    c[3] = cadd(E3, w3o); c[7] = csub(E3, w3o);
}

// ---------- fp32 Stockham passes (generic swz; used by K1/K5) ----------
template<int M>
__device__ __forceinline__ void pass8(const float2* __restrict__ A, float2* __restrict__ B,
                                      int rows, const float2* __restrict__ tw, int tid, int nth) {
    int total = rows << 4;
    for (int idx = tid; idx < total; idx += nth) {
        int r = idx >> 4, t = idx & 15;
        int lo = t & (M - 1), hi = t - lo;
        int base = r << 7;
        float2 a[8], c[8];
        #pragma unroll
        for (int j = 0; j < 8; j++) a[j] = A[base + swz(t + 16 * j)];
        dft8(a, c);
        int p = 8 * hi + lo;
        B[base + swz(p)] = c[0];
        #pragma unroll
        for (int k = 1; k < 8; k++)
            B[base + swz(p + k * M)] = cmul(c[k], tw[(hi * k) & 127]);
    }
}

__device__ __forceinline__ void pass2f(const float2* __restrict__ A, float2* __restrict__ B,
                                       int rows, int tid, int nth) {
    int total = rows << 6;
    for (int idx = tid; idx < total; idx += nth) {
        int r = idx >> 6, t = idx & 63;
        int base = r << 7;
        float2 a0 = A[base + swz(t)];
        float2 a1 = A[base + swz(t + 64)];
        B[base + swz(t)]      = cadd(a0, a1);
        B[base + swz(t + 64)] = csub(a0, a1);
    }
}

__device__ __forceinline__ float2* fft128_r8(float2* A, float2* B, int rows,
                                             const float2* tw, int tid, int nth) {
    pass8<1>(A, B, rows, tw, tid, nth); __syncthreads();
    pass8<8>(B, A, rows, tw, tid, nth); __syncthreads();
    pass2f(A, B, rows, tid, nth);       __syncthreads();
    return B;
}

// ---------- radix-16x8 sparse passes for k_fft_k (swzc addressing) ----------
__device__ __forceinline__ float2 h2f(__half2 v){ return __half22float2(v); }
__device__ __forceinline__ __half2 f2h(float2 v){ return __floats2half2_rn(v.x, v.y); }

#define DFT4_CORE(c0, c1, c2, c3, d0, d1, d2, d3) do {            \
    float2 _e0 = cadd(c0, c2), _e1 = csub(c0, c2);                \
    float2 _o0 = cadd(c1, c3), _o1 = cmulni(csub(c1, c3));        \
    d0 = cadd(_e0, _o0); d1 = cadd(_e1, _o1);                     \
    d2 = csub(_e0, _o0); d3 = csub(_e1, _o1);                     \
} while (0)

__device__ __forceinline__ void pass16f_sp4(const float2* __restrict__ A, float2* __restrict__ B,
                                            int rows, const float2* __restrict__ tw, int tid, int nth) {
    int total = rows << 3;
    for (int idx = tid; idx < total; idx += nth) {
        int r = idx >> 3, t = idx & 7;
        int base = r << 7;
        float2 b0 = A[base + swzc(r, t)];
        float2 b1 = A[base + swzc(r, t + 8)];
        float2 b2 = A[base + swzc(r, t + 16)];
        float2 b3 = A[base + swzc(r, t + 24)];
        #pragma unroll
        for (int m = 0; m < 4; m++) {
            float2 c1 = cmul(b1, tw[(8  * m) & 127]);
            float2 c2 = cmul(b2, tw[(16 * m) & 127]);
            float2 c3 = cmul(b3, tw[(24 * m) & 127]);
            float2 d0, d1, d2, d3;
            DFT4_CORE(b0, c1, c2, c3, d0, d1, d2, d3);
            B[base + swzc(r, 16*t + m)]      = cmul(d0, tw[(t * (m))      & 127]);
            B[base + swzc(r, 16*t + m + 4)]  = cmul(d1, tw[(t * (m + 4))  & 127]);
            B[base + swzc(r, 16*t + m + 8)]  = cmul(d2, tw[(t * (m + 8))  & 127]);
            B[base + swzc(r, 16*t + m + 12)] = cmul(d3, tw[(t * (m + 12)) & 127]);
        }
    }
}

__device__ __forceinline__ void pass16h_sp4(const __half2* __restrict__ A, __half2* __restrict__ B,
                                            int rows, const float2* __restrict__ tw, int tid, int nth) {
    int total = rows << 3;
    for (int idx = tid; idx < total; idx += nth) {
        int r = idx >> 3, t = idx & 7;
        int base = r << 7;
        float2 b0 = h2f(A[base + swzc(r, t)]);
        float2 b1 = h2f(A[base + swzc(r, t + 8)]);
        float2 b2 = h2f(A[base + swzc(r, t + 16)]);
        float2 b3 = h2f(A[base + swzc(r, t + 24)]);
        #pragma unroll
        for (int m = 0; m < 4; m++) {
            float2 c1 = cmul(b1, tw[(8  * m) & 127]);
            float2 c2 = cmul(b2, tw[(16 * m) & 127]);
            float2 c3 = cmul(b3, tw[(24 * m) & 127]);
            float2 d0, d1, d2, d3;
            DFT4_CORE(b0, c1, c2, c3, d0, d1, d2, d3);
            B[base + swzc(r, 16*t + m)]      = f2h(cmul(d0, tw[(t * (m))      & 127]));
            B[base + swzc(r, 16*t + m + 4)]  = f2h(cmul(d1, tw[(t * (m + 4))  & 127]));
            B[base + swzc(r, 16*t + m + 8)]  = f2h(cmul(d2, tw[(t * (m + 8))  & 127]));
            B[base + swzc(r, 16*t + m + 12)] = f2h(cmul(d3, tw[(t * (m + 12)) & 127]));
        }
    }
}

__device__ __forceinline__ void pass8f_nt(const float2* __restrict__ A, float2* __restrict__ B,
                                          int rows, int tid, int nth) {
    int total = rows << 4;
    for (int idx = tid; idx < total; idx += nth) {
        int r = idx >> 4, t = idx & 15;
        int base = r << 7;
        float2 a[8], c[8];
        #pragma unroll
        for (int j = 0; j < 8; j++) a[j] = A[base + swzc(r, t + 16 * j)];
        dft8(a, c);
        #pragma unroll
        for (int k = 0; k < 8; k++)
            B[base + swzc(r, t + 16 * k)] = c[k];
    }
}

__device__ __forceinline__ void pass8h_nt(const __half2* __restrict__ A, __half2* __restrict__ B,
                                          int rows, int tid, int nth) {
    int total = rows << 4;
    for (int idx = tid; idx < total; idx += nth) {
        int r = idx >> 4, t = idx & 15;
        int base = r << 7;
        float2 a[8], c[8];
        #pragma unroll
        for (int j = 0; j < 8; j++) a[j] = h2f(A[base + swzc(r, t + 16 * j)]);
        dft8(a, c);
        #pragma unroll
        for (int k = 0; k < 8; k++)
            B[base + swzc(r, t + 16 * k)] = f2h(c[k]);
    }
}

// ---------------- K1: 2D rFFT of x -> g_xf[bc][bin] ----------------
__global__ void __launch_bounds__(512) k_fft_x(const float* __restrict__ x) {
    extern __shared__ float2 sm[];
    float2* tw = sm;
    float2* bufA = sm + 128;
    float2* bufB = bufA + NBIN;
    int tid = threadIdx.x, nth = blockDim.x;
    int bc = blockIdx.x;

    make_twiddles(tw, tid);
    const float* img = x + (size_t)bc * HH * WW;
    for (int idx = tid; idx < 64 * 128; idx += nth) {
        int r = idx >> 7, n = idx & 127;
        bufA[(r << 7) + swz(n)] = make_float2(img[(2 * r) * WW + n],
                                              img[(2 * r + 1) * WW + n]);
    }
    __syncthreads();
    float2* P = fft128_r8(bufA, bufB, 64, tw, tid, nth);
    float2* S = bufA;
    for (int idx = tid; idx < 64 * NF; idx += nth) {
        int r = idx / NF, k = idx - r * NF;
        float2 Zk = P[(r << 7) + swz(k)];
        float2 Zn = P[(r << 7) + swz((128 - k) & 127)];
        float2 Ar = make_float2(0.5f * (Zk.x + Zn.x), 0.5f * (Zk.y - Zn.y));
        float2 Br = make_float2(0.5f * (Zk.y + Zn.y), 0.5f * (Zn.x - Zk.x));
        S[(k << 7) + swz(2 * r)]     = Ar;
        S[(k << 7) + swz(2 * r + 1)] = Br;
    }
    __syncthreads();
    float2* Ff = fft128_r8(bufA, bufB, NF, tw, tid, nth);
    float2* ob = g_xf + (size_t)bc * NBIN;
    for (int bin = tid; bin < NBIN; bin += nth) {
        int h = bin & 127;
        ob[bin] = Ff[(bin - h) + swz(h)];    // bin = k*128+h ; (k<<7) = bin-h
    }
}

// ---------------- K2: 2D rFFT of filters (plain, fp16) -> g_kfn[c*F+f][bin] ----------------
#define SMEM_K2 (1024 + 2 * NBIN * 4)    // 67,584 B
__global__ void __launch_bounds__(512, 2) k_fft_k(const float* __restrict__ filt) {
    extern __shared__ char smk[];
    float2*  tw = (float2*)smk;
    __half2* CA = (__half2*)(smk + 1024);
    __half2* CB = (__half2*)(smk + 1024 + NBIN * 4);
    float2*  RA = (float2*)CB;                              // 16 KB
    float2*  RB = (float2*)(smk + 1024 + NBIN * 4 + 16384); // 16 KB (inside CB region)
    int tid = threadIdx.x, nth = blockDim.x;
    int fc = blockIdx.x;   // f*C + c (natural input order)
    int f = fc >> 7, c = fc & 127;

    make_twiddles(tw, tid);
    for (int idx = tid; idx < 16 * 128; idx += nth)
        RA[idx] = make_float2(0.f, 0.f);
    __syncthreads();
    const float* kimg = filt + (size_t)fc * KHH * KWW;
    for (int idx = tid; idx < KHH * KWW; idx += nth) {
        int i = idx / KWW, j = idx - i * KWW;
        float v = kimg[idx];
        int r = i >> 1;
        if (i & 1) RA[(r << 7) + swzc(r, j)].y = v;
        else       RA[(r << 7) + swzc(r, j)].x = v;
    }
    __syncthreads();
    pass16f_sp4(RA, RB, 16, tw, tid, nth); __syncthreads();
    pass8f_nt(RB, RA, 16, tid, nth);       __syncthreads();
    for (int idx = tid; idx < 16 * NF; idx += nth) {
        int r = idx / NF, k = idx - r * NF;
        float2 Zk = RA[(r << 7) + swzc(r, k)];
        float2 Zn = RA[(r << 7) + swzc(r, (128 - k) & 127)];
        float2 Ar = make_float2(0.5f * (Zk.x + Zn.x), 0.5f * (Zk.y - Zn.y));
        float2 Br = make_float2(0.5f * (Zk.y + Zn.y), 0.5f * (Zn.x - Zk.x));
        CA[(k << 7) + swzc(k, 2 * r)]     = f2h(Ar);
        CA[(k << 7) + swzc(k, 2 * r + 1)] = f2h(Br);
    }
    __syncthreads();
    pass16h_sp4(CA, CB, NF, tw, tid, nth); __syncthreads();
    pass8h_nt(CB, CA, NF, tid, nth);       __syncthreads();
    __half2* ob = g_kfn + (size_t)(c * F + f) * NBIN;
    for (int bin = tid; bin < NBIN; bin += nth) {
        int h = bin & 127;
        ob[bin] = CA[(bin - h) + swzc(bin >> 7, h)];
    }
}

// ---------------- K4: 4-bin complex GEMM with fp32 P/Q/Qm planes ----------------
// CTA: 4 bins x 16 b x 128 f, 256 threads, 2 CTAs/SM, 32 stages of 4 c.
// warp (8): binq = wid & 1 (bin pair), b0 = (wid >> 1) * 4 (4 batches); f = lane + 32j.
// Stage: cp.async raw fp16 -> convert ONCE into fp32 planes P/Q/Qm -> pure LDS+FMA loop.
// accRE += Xr*P + Xi*Q ; accIM += Xi*P + Xr*Qm  (Qm = -Q)
//   per bin: re = Xr*p + Xi*q , im = Xi*p - Xr*q  ==  X * conj(K)  ✓
// Plane word addr: W(cf) = 4*PERM(cf), PERM(cf) = cf ^ ((cf>>3)&3)  — BIJECTIVE (no
// range collisions, unlike an additive pad), 8B-aligned, <=2-way conflicts/half-warp.
#define NB4 4
#define K4_CH 4
#define K4_NSTG 32
#define PB_OFF  65536
#define QB_OFF  (PB_OFF + 8448)
#define QM_OFF  (QB_OFF + 8448)
#define RAW_OFF (QM_OFF + 8448)              // 90,880
#define SMEM_K4 (RAW_OFF + 2 * 8192)         // 107,264 B
#define KPERM(cf) ((cf) ^ (((cf) >> 3) & 3))

__global__ void __launch_bounds__(256, 2) k_gemm4c() {
    extern __shared__ char s4[];
    float* xre = (float*)s4;                       // [bc][4 bins]
    float* xim = (float*)(s4 + 32768);
    float* Ppl = (float*)(s4 + PB_OFF);
    float* Qpl = (float*)(s4 + QB_OFF);
    float* Mpl = (float*)(s4 + QM_OFF);
    uint32_t rawb = smem_u32(s4 + RAW_OFF);
    int tid = threadIdx.x, lane = tid & 31, wid = tid >> 5;
    int bin0 = blockIdx.x * NB4;
    int binq = wid & 1;
    int b0   = (wid >> 1) * 4;

    // per-thread plane word offsets for j = 0..3 (bijective perm + binq)
    int wjq[4];
    #pragma unroll
    for (int j = 0; j < 4; j++) {
        int lj = lane + 32 * j;
        wjq[j] = 4 * KPERM(lj) + 2 * binq;
    }

    // ---- X prologue: de-interleave g_xf[bc][bin0..3] into xre/xim [bc][4] ----
    #pragma unroll
    for (int m = 0; m < 16; m++) {
        int t = m * 256 + tid;          // 4096 float4 chunks
        int bc = t >> 1, quad = t & 1;  // quad = bin pair
        float4 v = *(const float4*)&g_xf[(size_t)bc * NBIN + bin0 + 2 * quad];
        int w = bc * 4 + 2 * quad;
        *(float2*)&xre[w] = make_float2(v.x, v.z);
        *(float2*)&xim[w] = make_float2(v.y, v.w);
    }
    // ---- kf raw prologue: stages 0,1 (4 c each; row (c,f) = 16B = 2 cp8) ----
    #pragma unroll
    for (int s = 0; s < 2; s++) {
        #pragma unroll
        for (int r = 0; r < 4; r++) {
            int m = r * 256 + tid;          // 1024 8-byte chunks per stage
            int cf = m >> 1, q = m & 1;
            int cc = cf >> 7, f = cf & 127;
            uint32_t dst = rawb + (uint32_t)(s * 8192 + cf * 16 + q * 8);
            const void* src = g_kfn + (size_t)((s * K4_CH + cc) * 128 + f) * NBIN + bin0 + q * 2;
            cp8(dst, src);
        }
        asm volatile("cp.async.commit_group;");
    }

    unsigned long long accRE[16], accIM[16];
    #pragma unroll
    for (int i = 0; i < 16; i++) { accRE[i] = 0ULL; accIM[i] = 0ULL; }

    #pragma unroll 1
    for (int s = 0; s < K4_NSTG; s++) {
        if (s < K4_NSTG - 1) asm volatile("cp.async.wait_group 1;");
        else                 asm volatile("cp.async.wait_group 0;");
        __syncthreads();   // raw[s&1] ready AND planes free (prev compute done)
        // ---- convert raw fp16 -> fp32 planes (each (c,f) once) ----
        const char* rb = s4 + RAW_OFF + (s & 1) * 8192;
        #pragma unroll
        for (int r = 0; r < 2; r++) {
            int cf = r * 256 + tid;
            uint4 kk = *(const uint4*)(rb + cf * 16);
            float2 f0 = h2f(*reinterpret_cast<__half2*>(&kk.x));
            float2 f1 = h2f(*reinterpret_cast<__half2*>(&kk.y));
            float2 f2 = h2f(*reinterpret_cast<__half2*>(&kk.z));
            float2 f3 = h2f(*reinterpret_cast<__half2*>(&kk.w));
            int W = 4 * KPERM(cf);
            *(float2*)&Ppl[W]     = make_float2(f0.x, f1.x);
            *(float2*)&Ppl[W + 2] = make_float2(f2.x, f3.x);
            *(float2*)&Qpl[W]     = make_float2(f0.y, f1.y);
            *(float2*)&Qpl[W + 2] = make_float2(f2.y, f3.y);
            *(float2*)&Mpl[W]     = make_float2(-f0.y, -f1.y);
            *(float2*)&Mpl[W + 2] = make_float2(-f2.y, -f3.y);
        }
        __syncthreads();   // planes ready; raw[s&1] free to refill
        if (s < K4_NSTG - 2) {
            #pragma unroll
            for (int r = 0; r < 4; r++) {
                int m = r * 256 + tid;
                int cf = m >> 1, q = m & 1;
                int cc = cf >> 7, f = cf & 127;
                uint32_t dst = rawb + (uint32_t)((s & 1) * 8192 + cf * 16 + q * 8);
                const void* src = g_kfn + (size_t)(((s + 2) * K4_CH + cc) * 128 + f) * NBIN + bin0 + q * 2;
                cp8(dst, src);
            }
        }
        asm volatile("cp.async.commit_group;");
        // ---- compute: pure LDS + FMA ----
        #pragma unroll
        for (int cc = 0; cc < K4_CH; cc++) {
            int c = s * K4_CH + cc;
            unsigned long long Xr[4], Xi[4];
            #pragma unroll
            for (int i = 0; i < 4; i++) {
                int wx = ((b0 + i) * 128 + c) * 4 + 2 * binq;
                Xr[i] = *(const unsigned long long*)&xre[wx];
                Xi[i] = *(const unsigned long long*)&xim[wx];
            }
            #pragma unroll
            for (int j = 0; j < 4; j++) {
                int W = cc * 512 + wjq[j];
                unsigned long long Pp = *(const unsigned long long*)&Ppl[W];
                unsigned long long Qq = *(const unsigned long long*)&Qpl[W];
                unsigned long long Qm = *(const unsigned long long*)&Mpl[W];
                #pragma unroll
                for (int i = 0; i < 4; i++) {
                    asm("fma.rn.f32x2 %0, %1, %2, %0;" : "+l"(accRE[i * 4 + j]) : "l"(Xr[i]), "l"(Pp));
                    asm("fma.rn.f32x2 %0, %1, %2, %0;" : "+l"(accRE[i * 4 + j]) : "l"(Xi[i]), "l"(Qq));
                    asm("fma.rn.f32x2 %0, %1, %2, %0;" : "+l"(accIM[i * 4 + j]) : "l"(Xi[i]), "l"(Pp));
                    asm("fma.rn.f32x2 %0, %1, %2, %0;" : "+l"(accIM[i * 4 + j]) : "l"(Xr[i]), "l"(Qm));
                }
            }
        }
    }

    // ---- epilogue: write of^T in place into g_xf[bf][bin] ----
    #pragma unroll
    for (int i = 0; i < 4; i++) {
        #pragma unroll
        for (int j = 0; j < 4; j++) {
            float2 re, im;
            asm("mov.b64 {%0,%1}, %2;" : "=f"(re.x), "=f"(re.y) : "l"(accRE[i * 4 + j]));
            asm("mov.b64 {%0,%1}, %2;" : "=f"(im.x), "=f"(im.y) : "l"(accIM[i * 4 + j]));
            int bf = (b0 + i) * 128 + lane + 32 * j;
            *(float4*)&g_xf[(size_t)bf * NBIN + bin0 + 2 * binq] =
                make_float4(re.x, im.x, re.y, im.y);
        }
    }
}

// ---------------- K5: 2D irFFT + slice + bias (reads of^T from g_xf) ----------------
__global__ void __launch_bounds__(512) k_ifft(float* __restrict__ out,
                                              const float* __restrict__ bias) {
    extern __shared__ float2 sm[];
    float2* tw = sm;
    float2* bufA = sm + 128;
    float2* bufB = bufA + NBIN;
    int tid = threadIdx.x, nth = blockDim.x;
    int bf = blockIdx.x;
    int f  = bf & 127;

    make_twiddles(tw, tid);
    const float2* src = g_xf + (size_t)bf * NBIN;    // of^T row, coalesced
    for (int bin = tid; bin < NBIN; bin += nth) {
        float2 v = src[bin];
        int h = bin & 127;
        bufA[(bin - h) + swz(h)] = make_float2(v.x, -v.y);
    }
    __syncthreads();
    float2* R = fft128_r8(bufA, bufB, NF, tw, tid, nth);
    float2* T = bufA;
    for (int idx = tid; idx < 64 * 128; idx += nth) {
        int r = idx >> 7, k = idx & 127;
        float2 val;
        if (k <= 64) {
            float2 a = R[(k << 7) + swz(2 * r)];
            float2 b = R[(k << 7) + swz(2 * r + 1)];
            val = make_float2(a.x + b.y, a.y - b.x);
        } else {
            int kk = 128 - k;
            float2 a = R[(kk << 7) + swz(2 * r)];
            float2 b = R[(kk << 7) + swz(2 * r + 1)];
            val = make_float2(a.x - b.y, -a.y - b.x);
        }
        T[(r << 7) + swz(k)] = val;
    }
    __syncthreads();
    float2* Y = fft128_r8(bufA, bufB, 64, tw, tid, nth);
    const float inv = 1.0f / 16384.0f;
    float bv = bias[f];
    float* ob = out + (size_t)bf * OH * OW;
    for (int idx = tid; idx < OH * OW; idx += nth) {
        int oh = idx / OW, ow = idx - oh * OW;
        float2 y = Y[((oh >> 1) << 7) + swz(ow)];
        float v = (oh & 1) ? -y.y : y.x;
        ob[idx] = v * inv + bv;
    }
}

// ---------------- launch ----------------
extern "C" void kernel_launch(void* const* d_in, const int* in_sizes, int n_in,
                              void* d_out, int out_size) {
    const float* x    = (const float*)d_in[0];
    const float* filt = (const float*)d_in[1];
    const float* bias = (const float*)d_in[2];
    float* out = (float*)d_out;

    int smFFT = (128 + 2 * NBIN) * (int)sizeof(float2);   // 134,144 B
    cudaFuncSetAttribute(k_fft_x,  cudaFuncAttributeMaxDynamicSharedMemorySize, smFFT);
    cudaFuncSetAttribute(k_fft_k,  cudaFuncAttributeMaxDynamicSharedMemorySize, SMEM_K2);
    cudaFuncSetAttribute(k_ifft,   cudaFuncAttributeMaxDynamicSharedMemorySize, smFFT);
    cudaFuncSetAttribute(k_gemm4c, cudaFuncAttributeMaxDynamicSharedMemorySize, SMEM_K4);

    k_fft_x<<<BC, 512, smFFT>>>(x);
    k_fft_k<<<FC, 512, SMEM_K2>>>(filt);
    k_gemm4c<<<NBIN / NB4, 256, SMEM_K4>>>();
    k_ifft<<<BC, 512, smFFT>>>(out, bias);
}

// round 15
// speedup vs baseline: 1.3031x; 1.3031x over previous
#include <cuda_runtime.h>
#include <cuda_fp16.h>
#include <cstdint>
#include <math.h>

#define BB 16
#define C  128
#define F  128
#define HH 128
#define WW 128
#define KHH 31
#define KWW 31
#define OH 98
#define OW 98
#define NF 65          // rfft bins along W
#define NBIN (HH*NF)   // 8320 ; bin = k*128 + h  (k-major)
#define BC (BB*C)      // 2048
#define FC (F*C)       // 16384

// -------- scratch (device globals; no allocation allowed) --------
__device__ float2  g_xf [(size_t)BC  * NBIN];   // [b*C+c][bin]; K4 overwrites in place with of^T [b*F+f][bin]
__device__ __half2 g_kfn[(size_t)FC  * NBIN];   // [c*F+f][bin]  (plain fft, fp16)

// ---------------- helpers ----------------
__device__ __forceinline__ int swz(int w) { return w ^ ((w >> 4) & 7); }
// row-aware swizzle
__device__ __forceinline__ int swzc(int r, int w) {
    int v = w ^ ((r & 3) << 3);
    return v ^ ((v >> 4) & 7);
}
__device__ __forceinline__ float2 cadd(float2 a, float2 b){return make_float2(a.x+b.x, a.y+b.y);}
__device__ __forceinline__ float2 csub(float2 a, float2 b){return make_float2(a.x-b.x, a.y-b.y);}
__device__ __forceinline__ float2 cmul(float2 a, float2 b){return make_float2(a.x*b.x-a.y*b.y, a.x*b.y+a.y*b.x);}
__device__ __forceinline__ float2 cmulni(float2 a){return make_float2(a.y, -a.x);}  // a * (-i)

__device__ __forceinline__ void make_twiddles(float2* tw, int tid) {
    if (tid < 128) {
        float s, c;
        sincosf(-6.283185307179586f * (float)tid / 128.0f, &s, &c);
        tw[tid] = make_float2(c, s);
    }
}

__device__ __forceinline__ uint32_t smem_u32(const void* p) {
    uint32_t a;
    asm("{ .reg .u64 t; cvta.to.shared.u64 t, %1; cvt.u32.u64 %0, t; }" : "=r"(a) : "l"(p));
    return a;
}
__device__ __forceinline__ void cp8(uint32_t dst, const void* src) {
    asm volatile("cp.async.ca.shared.global [%0], [%1], 8;" :: "r"(dst), "l"(src));
}

// DFT8 natural order: c[k] = sum_j a[j] W8^{jk}
__device__ __forceinline__ void dft8(const float2* a, float2* c) {
    float2 t0 = cadd(a[0], a[4]), t1 = csub(a[0], a[4]);
    float2 t2 = cadd(a[2], a[6]), t3 = csub(a[2], a[6]);
    float2 m3 = cmulni(t3);
    float2 E0 = cadd(t0, t2), E2 = csub(t0, t2);
    float2 E1 = cadd(t1, m3), E3 = csub(t1, m3);
    t0 = cadd(a[1], a[5]); t1 = csub(a[1], a[5]);
    t2 = cadd(a[3], a[7]); t3 = csub(a[3], a[7]);
    m3 = cmulni(t3);
    float2 O0 = cadd(t0, t2), O2 = csub(t0, t2);
    float2 O1 = cadd(t1, m3), O3 = csub(t1, m3);
    const float s = 0.70710678118654752f;
    float2 w1o = make_float2(s * (O1.x + O1.y), s * (O1.y - O1.x));
    float2 w2o = cmulni(O2);
    float2 w3o = make_float2(s * (O3.y - O3.x), s * (-O3.x - O3.y));
    c[0] = cadd(E0, O0);  c[4] = csub(E0, O0);
    c[1] = cadd(E1, w1o); c[5] = csub(E1, w1o);
    c[2] = cadd(E2, w2o); c[6] = csub(E2, w2o);
    c[3] = cadd(E3, w3o); c[7] = csub(E3, w3o);
}

#define DFT4_CORE(c0, c1, c2, c3, d0, d1, d2, d3) do {            \
    float2 _e0 = cadd(c0, c2), _e1 = csub(c0, c2);                \
    float2 _o0 = cadd(c1, c3), _o1 = cmulni(csub(c1, c3));        \
    d0 = cadd(_e0, _o0); d1 = cadd(_e1, _o1);                     \
    d2 = csub(_e0, _o0); d3 = csub(_e1, _o1);                     \
} while (0)

// ---------- shared passes (swzc addressing) ----------
__device__ __forceinline__ float2 h2f(__half2 v){ return __half22float2(v); }
__device__ __forceinline__ __half2 f2h(float2 v){ return __floats2half2_rn(v.x, v.y); }

// dense radix-16 first pass (M=1): B[16t+k] = DFT16(a)[k] * W128^{t k}
__device__ __forceinline__ void pass16f(const float2* __restrict__ A, float2* __restrict__ B,
                                        int rows, const float2* __restrict__ tw, int tid, int nth) {
    int total = rows << 3;
    for (int idx = tid; idx < total; idx += nth) {
        int r = idx >> 3, t = idx & 7;
        int base = r << 7;
        float2 ae[8], ao[8], E[8], O[8];
        #pragma unroll
        for (int m = 0; m < 8; m++) {
            ae[m] = A[base + swzc(r, t + 16 * m)];
            ao[m] = A[base + swzc(r, t + 8 + 16 * m)];
        }
        dft8(ae, E);
        dft8(ao, O);
        #pragma unroll
        for (int k = 0; k < 8; k++) {
            float2 wo = cmul(O[k], tw[(8 * k) & 127]);
            float2 c0 = cadd(E[k], wo);
            float2 c1 = csub(E[k], wo);
            B[base + swzc(r, 16 * t + k)]     = cmul(c0, tw[(t * k) & 127]);
            B[base + swzc(r, 16 * t + k + 8)] = cmul(c1, tw[(t * (k + 8)) & 127]);
        }
    }
}

// sparse radix-16 first pass (only inputs 0..31 nonzero) — fp32 / fp16 variants
__device__ __forceinline__ void pass16f_sp4(const float2* __restrict__ A, float2* __restrict__ B,
                                            int rows, const float2* __restrict__ tw, int tid, int nth) {
    int total = rows << 3;
    for (int idx = tid; idx < total; idx += nth) {
        int r = idx >> 3, t = idx & 7;
        int base = r << 7;
        float2 b0 = A[base + swzc(r, t)];
        float2 b1 = A[base + swzc(r, t + 8)];
        float2 b2 = A[base + swzc(r, t + 16)];
        float2 b3 = A[base + swzc(r, t + 24)];
        #pragma unroll
        for (int m = 0; m < 4; m++) {
            float2 c1 = cmul(b1, tw[(8  * m) & 127]);
            float2 c2 = cmul(b2, tw[(16 * m) & 127]);
            float2 c3 = cmul(b3, tw[(24 * m) & 127]);
            float2 d0, d1, d2, d3;
            DFT4_CORE(b0, c1, c2, c3, d0, d1, d2, d3);
            B[base + swzc(r, 16*t + m)]      = cmul(d0, tw[(t * (m))      & 127]);
            B[base + swzc(r, 16*t + m + 4)]  = cmul(d1, tw[(t * (m + 4))  & 127]);
            B[base + swzc(r, 16*t + m + 8)]  = cmul(d2, tw[(t * (m + 8))  & 127]);
            B[base + swzc(r, 16*t + m + 12)] = cmul(d3, tw[(t * (m + 12)) & 127]);
        }
    }
}

__device__ __forceinline__ void pass16h_sp4(const __half2* __restrict__ A, __half2* __restrict__ B,
                                            int rows, const float2* __restrict__ tw, int tid, int nth) {
    int total = rows << 3;
    for (int idx = tid; idx < total; idx += nth) {
        int r = idx >> 3, t = idx & 7;
        int base = r << 7;
        float2 b0 = h2f(A[base + swzc(r, t)]);
        float2 b1 = h2f(A[base + swzc(r, t + 8)]);
        float2 b2 = h2f(A[base + swzc(r, t + 16)]);
        float2 b3 = h2f(A[base + swzc(r, t + 24)]);
        #pragma unroll
        for (int m = 0; m < 4; m++) {
            float2 c1 = cmul(b1, tw[(8  * m) & 127]);
            float2 c2 = cmul(b2, tw[(16 * m) & 127]);
            float2 c3 = cmul(b3, tw[(24 * m) & 127]);
            float2 d0, d1, d2, d3;
            DFT4_CORE(b0, c1, c2, c3, d0, d1, d2, d3);
            B[base + swzc(r, 16*t + m)]      = f2h(cmul(d0, tw[(t * (m))      & 127]));
            B[base + swzc(r, 16*t + m + 4)]  = f2h(cmul(d1, tw[(t * (m + 4))  & 127]));
            B[base + swzc(r, 16*t + m + 8)]  = f2h(cmul(d2, tw[(t * (m + 8))  & 127]));
            B[base + swzc(r, 16*t + m + 12)] = f2h(cmul(d3, tw[(t * (m + 12)) & 127]));
        }
    }
}

// final radix-8 pass (M=16), hi==0 -> no twiddle
__device__ __forceinline__ void pass8f_nt(const float2* __restrict__ A, float2* __restrict__ B,
                                          int rows, int tid, int nth) {
    int total = rows << 4;
    for (int idx = tid; idx < total; idx += nth) {
        int r = idx >> 4, t = idx & 15;
        int base = r << 7;
        float2 a[8], c[8];
        #pragma unroll
        for (int j = 0; j < 8; j++) a[j] = A[base + swzc(r, t + 16 * j)];
        dft8(a, c);
        #pragma unroll
        for (int k = 0; k < 8; k++)
            B[base + swzc(r, t + 16 * k)] = c[k];
    }
}

__device__ __forceinline__ void pass8h_nt(const __half2* __restrict__ A, __half2* __restrict__ B,
                                          int rows, int tid, int nth) {
    int total = rows << 4;
    for (int idx = tid; idx < total; idx += nth) {
        int r = idx >> 4, t = idx & 15;
        int base = r << 7;
        float2 a[8], c[8];
        #pragma unroll
        for (int j = 0; j < 8; j++) a[j] = h2f(A[base + swzc(r, t + 16 * j)]);
        dft8(a, c);
        #pragma unroll
        for (int k = 0; k < 8; k++)
            B[base + swzc(r, t + 16 * k)] = f2h(c[k]);
    }
}

// 2-pass 128-pt FFT: A -> B -> A ; result in A
__device__ __forceinline__ float2* fft128_r16(float2* A, float2* B, int rows,
                                              const float2* tw, int tid, int nth) {
    pass16f(A, B, rows, tw, tid, nth); __syncthreads();
    pass8f_nt(B, A, rows, tid, nth);   __syncthreads();
    return A;
}

// ---------------- K1: 2D rFFT of x -> g_xf[bc][bin] ----------------
__global__ void __launch_bounds__(512) k_fft_x(const float* __restrict__ x) {
    extern __shared__ float2 sm[];
    float2* tw = sm;
    float2* bufA = sm + 128;
    float2* bufB = bufA + NBIN;
    int tid = threadIdx.x, nth = blockDim.x;
    int bc = blockIdx.x;

    make_twiddles(tw, tid);
    const float* img = x + (size_t)bc * HH * WW;
    for (int idx = tid; idx < 64 * 128; idx += nth) {
        int r = idx >> 7, n = idx & 127;
        bufA[(r << 7) + swzc(r, n)] = make_float2(img[(2 * r) * WW + n],
                                                  img[(2 * r + 1) * WW + n]);
    }
    __syncthreads();
    float2* P = fft128_r16(bufA, bufB, 64, tw, tid, nth);   // result in bufA
    // unpack rfft rows -> S[k][h'] in bufB (65 rows)
    for (int idx = tid; idx < 64 * NF; idx += nth) {
        int r = idx / NF, k = idx - r * NF;
        float2 Zk = P[(r << 7) + swzc(r, k)];
        float2 Zn = P[(r << 7) + swzc(r, (128 - k) & 127)];
        float2 Ar = make_float2(0.5f * (Zk.x + Zn.x), 0.5f * (Zk.y - Zn.y));
        float2 Br = make_float2(0.5f * (Zk.y + Zn.y), 0.5f * (Zn.x - Zk.x));
        bufB[(k << 7) + swzc(k, 2 * r)]     = Ar;
        bufB[(k << 7) + swzc(k, 2 * r + 1)] = Br;
    }
    __syncthreads();
    float2* Ff = fft128_r16(bufB, bufA, NF, tw, tid, nth);  // result in bufB
    float2* ob = g_xf + (size_t)bc * NBIN;
    for (int bin = tid; bin < NBIN; bin += nth) {
        int h = bin & 127;
        ob[bin] = Ff[(bin - h) + swzc(bin >> 7, h)];        // bin = k*128+h
    }
}

// ---------------- K2: 2D rFFT of filters (plain, fp16) -> g_kfn[c*F+f][bin] ----------------
#define SMEM_K2 (1024 + 2 * NBIN * 4)    // 67,584 B
__global__ void __launch_bounds__(512, 2) k_fft_k(const float* __restrict__ filt) {
    extern __shared__ char smk[];
    float2*  tw = (float2*)smk;
    __half2* CA = (__half2*)(smk + 1024);
    __half2* CB = (__half2*)(smk + 1024 + NBIN * 4);
    float2*  RA = (float2*)CB;                              // 16 KB
    float2*  RB = (float2*)(smk + 1024 + NBIN * 4 + 16384); // 16 KB (inside CB region)
    int tid = threadIdx.x, nth = blockDim.x;
    int fc = blockIdx.x;   // f*C + c (natural input order)
    int f = fc >> 7, c = fc & 127;

    make_twiddles(tw, tid);
    for (int idx = tid; idx < 16 * 128; idx += nth)
        RA[idx] = make_float2(0.f, 0.f);
    __syncthreads();
    const float* kimg = filt + (size_t)fc * KHH * KWW;
    for (int idx = tid; idx < KHH * KWW; idx += nth) {
        int i = idx / KWW, j = idx - i * KWW;
        float v = kimg[idx];
        int r = i >> 1;
        if (i & 1) RA[(r << 7) + swzc(r, j)].y = v;
        else       RA[(r << 7) + swzc(r, j)].x = v;
    }
    __syncthreads();
    pass16f_sp4(RA, RB, 16, tw, tid, nth); __syncthreads();
    pass8f_nt(RB, RA, 16, tid, nth);       __syncthreads();
    for (int idx = tid; idx < 16 * NF; idx += nth) {
        int r = idx / NF, k = idx - r * NF;
        float2 Zk = RA[(r << 7) + swzc(r, k)];
        float2 Zn = RA[(r << 7) + swzc(r, (128 - k) & 127)];
        float2 Ar = make_float2(0.5f * (Zk.x + Zn.x), 0.5f * (Zk.y - Zn.y));
        float2 Br = make_float2(0.5f * (Zk.y + Zn.y), 0.5f * (Zn.x - Zk.x));
        CA[(k << 7) + swzc(k, 2 * r)]     = f2h(Ar);
        CA[(k << 7) + swzc(k, 2 * r + 1)] = f2h(Br);
    }
    __syncthreads();
    pass16h_sp4(CA, CB, NF, tw, tid, nth); __syncthreads();
    pass8h_nt(CB, CA, NF, tid, nth);       __syncthreads();
    __half2* ob = g_kfn + (size_t)(c * F + f) * NBIN;
    for (int bin = tid; bin < NBIN; bin += nth) {
        int h = bin & 127;
        ob[bin] = CA[(bin - h) + swzc(bin >> 7, h)];
    }
}

// ---------------- K4: 4-bin complex GEMM (R12 proven version) ----------------
// CTA: 4 bins x 16 b x 128 f, K=128 c, 512 threads, 8 stages of 16 c.
// warp: binq = wid & 1 (bin pair), b0 = (wid >> 1) * 2 (2 batches); f = lane + 32j (4 f).
// accRE += Xr*Pp + Xi*Qq ; accIM += Xi*Pp + Xr*Qm  (Qm = -Qq)
//   per bin: re = Xr*p + Xi*q , im = Xi*p - Xr*q  ==  X * conj(K)  ✓
#define NB4 4
#define K4_CH 16
#define K4_XS_IM_OFF 32768
#define K4_KS_OFF    65536
#define K4_KSBUF_W   12288        // words per buffer (16c * 128f * 6)
#define SMEM_K4 (65536 + 2 * 49152)   // 163,840 B

__global__ void __launch_bounds__(512, 1) k_gemm4() {
    extern __shared__ char s4[];
    float* xre = (float*)s4;                      // [bc][4 bins]
    float* xim = (float*)(s4 + K4_XS_IM_OFF);
    float* ksf = (float*)(s4 + K4_KS_OFF);
    uint32_t ksb = smem_u32(s4 + K4_KS_OFF);
    int tid = threadIdx.x, lane = tid & 31, wid = tid >> 5;
    int bin0 = blockIdx.x * NB4;
    int binq = wid & 1;            // bin pair: bins bin0+2binq, +1
    int b0   = (wid >> 1) * 2;     // 2 batches

    #pragma unroll
    for (int m = 0; m < 8; m++) {
        int t = m * 512 + tid;
        int bc = t >> 1, quad = t & 1;
        float4 v = *(const float4*)&g_xf[(size_t)bc * NBIN + bin0 + 2 * quad];
        int w = bc * 4 + 2 * quad;
        *(float2*)&xre[w] = make_float2(v.x, v.z);
        *(float2*)&xim[w] = make_float2(v.y, v.w);
    }
    #pragma unroll
    for (int s = 0; s < 2; s++) {
        #pragma unroll
        for (int r = 0; r < 8; r++) {
            int m = r * 512 + tid;
            int cf = m >> 1, q = m & 1;
            int cc = cf >> 7, f = cf & 127;
            uint32_t dst = ksb + (uint32_t)(s * K4_KSBUF_W + (cc * 128 + f) * 6 + q * 2) * 4;
            const void* src = g_kfn + (size_t)((s * K4_CH + cc) * 128 + f) * NBIN + bin0 + q * 2;
            cp8(dst, src);
        }
        asm volatile("cp.async.commit_group;");
    }
    __syncthreads();

    unsigned long long accRE[8], accIM[8];
    #pragma unroll
    for (int i = 0; i < 8; i++) { accRE[i] = 0ULL; accIM[i] = 0ULL; }

    #pragma unroll 1
    for (int s = 0; s < 8; s++) {
        if (s < 7) asm volatile("cp.async.wait_group 1;");
        else       asm volatile("cp.async.wait_group 0;");
        __syncthreads();
        int kbase = (s & 1) * K4_KSBUF_W;
        #pragma unroll
        for (int cc = 0; cc < K4_CH; cc++) {
            int c = s * K4_CH + cc;
            unsigned long long Pp[4], Qq[4], Qm[4];
            #pragma unroll
            for (int j = 0; j < 4; j++) {
                int w = kbase + (cc * 128 + lane + 32 * j) * 6 + 2 * binq;
                uint2 kk = *(const uint2*)&ksf[w];
                float2 kA = h2f(*reinterpret_cast<__half2*>(&kk.x));
                float2 kB = h2f(*reinterpret_cast<__half2*>(&kk.y));
                float nqA = -kA.y, nqB = -kB.y;
                asm("mov.b64 %0, {%1,%2};" : "=l"(Pp[j]) : "f"(kA.x), "f"(kB.x));
                asm("mov.b64 %0, {%1,%2};" : "=l"(Qq[j]) : "f"(kA.y), "f"(kB.y));
                asm("mov.b64 %0, {%1,%2};" : "=l"(Qm[j]) : "f"(nqA),  "f"(nqB));
            }
            #pragma unroll
            for (int i = 0; i < 2; i++) {
                int wx = ((b0 + i) * 128 + c) * 4 + 2 * binq;
                unsigned long long Xr = *(const unsigned long long*)&xre[wx];
                unsigned long long Xi = *(const unsigned long long*)&xim[wx];
                #pragma unroll
                for (int j = 0; j < 4; j++) {
                    asm("fma.rn.f32x2 %0, %1, %2, %0;" : "+l"(accRE[i * 4 + j]) : "l"(Xr), "l"(Pp[j]));
                    asm("fma.rn.f32x2 %0, %1, %2, %0;" : "+l"(accRE[i * 4 + j]) : "l"(Xi), "l"(Qq[j]));
                    asm("fma.rn.f32x2 %0, %1, %2, %0;" : "+l"(accIM[i * 4 + j]) : "l"(Xi), "l"(Pp[j]));
                    asm("fma.rn.f32x2 %0, %1, %2, %0;" : "+l"(accIM[i * 4 + j]) : "l"(Xr), "l"(Qm[j]));
                }
            }
        }
        __syncthreads();
        if (s < 6) {
            #pragma unroll
            for (int r = 0; r < 8; r++) {
                int m = r * 512 + tid;
                int cf = m >> 1, q = m & 1;
                int cc = cf >> 7, f = cf & 127;
                uint32_t dst = ksb + (uint32_t)((s & 1) * K4_KSBUF_W + (cc * 128 + f) * 6 + q * 2) * 4;
                const void* src = g_kfn + (size_t)(((s + 2) * K4_CH + cc) * 128 + f) * NBIN + bin0 + q * 2;
                cp8(dst, src);
            }
        }
        asm volatile("cp.async.commit_group;");
    }

    #pragma unroll
    for (int i = 0; i < 2; i++) {
        #pragma unroll
        for (int j = 0; j < 4; j++) {
            float2 re, im;
            asm("mov.b64 {%0,%1}, %2;" : "=f"(re.x), "=f"(re.y) : "l"(accRE[i * 4 + j]));
            asm("mov.b64 {%0,%1}, %2;" : "=f"(im.x), "=f"(im.y) : "l"(accIM[i * 4 + j]));
            int bf = (b0 + i) * 128 + lane + 32 * j;
            *(float4*)&g_xf[(size_t)bf * NBIN + bin0 + 2 * binq] =
                make_float4(re.x, im.x, re.y, im.y);
        }
    }
}

// ---------------- K5: 2D irFFT + slice + bias (reads of^T from g_xf) ----------------
__global__ void __launch_bounds__(512) k_ifft(float* __restrict__ out,
                                              const float* __restrict__ bias) {
    extern __shared__ float2 sm[];
    float2* tw = sm;
    float2* bufA = sm + 128;
    float2* bufB = bufA + NBIN;
    int tid = threadIdx.x, nth = blockDim.x;
    int bf = blockIdx.x;
    int f  = bf & 127;

    make_twiddles(tw, tid);
    const float2* src = g_xf + (size_t)bf * NBIN;    // of^T row, coalesced
    for (int bin = tid; bin < NBIN; bin += nth) {
        float2 v = src[bin];
        int h = bin & 127;
        bufA[(bin - h) + swzc(bin >> 7, h)] = make_float2(v.x, -v.y);
    }
    __syncthreads();
    float2* R = fft128_r16(bufA, bufB, NF, tw, tid, nth);   // result in bufA
    // combine -> bufB rows r (64)
    for (int idx = tid; idx < 64 * 128; idx += nth) {
        int r = idx >> 7, kcol = idx & 127;
        float2 val;
        if (kcol <= 64) {
            float2 a = R[(kcol << 7) + swzc(kcol, 2 * r)];
            float2 b = R[(kcol << 7) + swzc(kcol, 2 * r + 1)];
            val = make_float2(a.x + b.y, a.y - b.x);
        } else {
            int kk = 128 - kcol;
            float2 a = R[(kk << 7) + swzc(kk, 2 * r)];
            float2 b = R[(kk << 7) + swzc(kk, 2 * r + 1)];
            val = make_float2(a.x - b.y, -a.y - b.x);
        }
        bufB[(r << 7) + swzc(r, kcol)] = val;
    }
    __syncthreads();
    float2* Y = fft128_r16(bufB, bufA, 64, tw, tid, nth);   // result in bufB
    const float inv = 1.0f / 16384.0f;
    float bv = bias[f];
    float* ob = out + (size_t)bf * OH * OW;
    for (int idx = tid; idx < OH * OW; idx += nth) {
        int oh = idx / OW, ow = idx - oh * OW;
        int r = oh >> 1;
        float2 y = Y[(r << 7) + swzc(r, ow)];
        float v = (oh & 1) ? -y.y : y.x;
        ob[idx] = v * inv + bv;
    }
}

// ---------------- launch ----------------
extern "C" void kernel_launch(void* const* d_in, const int* in_sizes, int n_in,
                              void* d_out, int out_size) {
    const float* x    = (const float*)d_in[0];
    const float* filt = (const float*)d_in[1];
    const float* bias = (const float*)d_in[2];
    float* out = (float*)d_out;

    int smFFT = (128 + 2 * NBIN) * (int)sizeof(float2);   // 134,144 B
    cudaFuncSetAttribute(k_fft_x, cudaFuncAttributeMaxDynamicSharedMemorySize, smFFT);
    cudaFuncSetAttribute(k_fft_k, cudaFuncAttributeMaxDynamicSharedMemorySize, SMEM_K2);
    cudaFuncSetAttribute(k_ifft,  cudaFuncAttributeMaxDynamicSharedMemorySize, smFFT);
    cudaFuncSetAttribute(k_gemm4, cudaFuncAttributeMaxDynamicSharedMemorySize, SMEM_K4);

    k_fft_x<<<BC, 512, smFFT>>>(x);
    k_fft_k<<<FC, 512, SMEM_K2>>>(filt);
    k_gemm4<<<NBIN / NB4, 512, SMEM_K4>>>();
    k_ifft<<<BC, 512, smFFT>>>(out, bias);
}

// round 16
// speedup vs baseline: 1.3348x; 1.0243x over previous
#include <cuda_runtime.h>
#include <cuda_fp16.h>
#include <cstdint>
#include <math.h>

#define BB 16
#define C  128
#define F  128
#define HH 128
#define WW 128
#define KHH 31
#define KWW 31
#define OH 98
#define OW 98
#define NF 65          // rfft bins along W
#define NBIN (HH*NF)   // 8320 ; bin = k*128 + h  (k-major)
#define BC (BB*C)      // 2048
#define FC (F*C)       // 16384

// -------- scratch (device globals; no allocation allowed) --------
__device__ float2  g_xf [(size_t)BC  * NBIN];   // [b*C+c][bin]; K4 overwrites in place with of^T [b*F+f][bin]
__device__ __half2 g_kfn[(size_t)FC  * NBIN];   // [c*F+f][bin]  (plain fft, fp16)

// ---------------- helpers ----------------
__device__ __forceinline__ int swz(int w) { return w ^ ((w >> 4) & 7); }
// row-aware swizzle
__device__ __forceinline__ int swzc(int r, int w) {
    int v = w ^ ((r & 3) << 3);
    return v ^ ((v >> 4) & 7);
}
__device__ __forceinline__ float2 cadd(float2 a, float2 b){return make_float2(a.x+b.x, a.y+b.y);}
__device__ __forceinline__ float2 csub(float2 a, float2 b){return make_float2(a.x-b.x, a.y-b.y);}
__device__ __forceinline__ float2 cmul(float2 a, float2 b){return make_float2(a.x*b.x-a.y*b.y, a.x*b.y+a.y*b.x);}
__device__ __forceinline__ float2 cmulni(float2 a){return make_float2(a.y, -a.x);}  // a * (-i)

__device__ __forceinline__ void make_twiddles(float2* tw, int tid) {
    if (tid < 128) {
        float s, c;
        sincosf(-6.283185307179586f * (float)tid / 128.0f, &s, &c);
        tw[tid] = make_float2(c, s);
    }
}

__device__ __forceinline__ uint32_t smem_u32(const void* p) {
    uint32_t a;
    asm("{ .reg .u64 t; cvta.to.shared.u64 t, %1; cvt.u32.u64 %0, t; }" : "=r"(a) : "l"(p));
    return a;
}
__device__ __forceinline__ void cp8(uint32_t dst, const void* src) {
    asm volatile("cp.async.ca.shared.global [%0], [%1], 8;" :: "r"(dst), "l"(src));
}

// DFT8 natural order: c[k] = sum_j a[j] W8^{jk}
__device__ __forceinline__ void dft8(const float2* a, float2* c) {
    float2 t0 = cadd(a[0], a[4]), t1 = csub(a[0], a[4]);
    float2 t2 = cadd(a[2], a[6]), t3 = csub(a[2], a[6]);
    float2 m3 = cmulni(t3);
    float2 E0 = cadd(t0, t2), E2 = csub(t0, t2);
    float2 E1 = cadd(t1, m3), E3 = csub(t1, m3);
    t0 = cadd(a[1], a[5]); t1 = csub(a[1], a[5]);
    t2 = cadd(a[3], a[7]); t3 = csub(a[3], a[7]);
    m3 = cmulni(t3);
    float2 O0 = cadd(t0, t2), O2 = csub(t0, t2);
    float2 O1 = cadd(t1, m3), O3 = csub(t1, m3);
    const float s = 0.70710678118654752f;
    float2 w1o = make_float2(s * (O1.x + O1.y), s * (O1.y - O1.x));
    float2 w2o = cmulni(O2);
    float2 w3o = make_float2(s * (O3.y - O3.x), s * (-O3.x - O3.y));
    c[0] = cadd(E0, O0);  c[4] = csub(E0, O0);
    c[1] = cadd(E1, w1o); c[5] = csub(E1, w1o);
    c[2] = cadd(E2, w2o); c[6] = csub(E2, w2o);
    c[3] = cadd(E3, w3o); c[7] = csub(E3, w3o);
}

#define DFT4_CORE(c0, c1, c2, c3, d0, d1, d2, d3) do {            \
    float2 _e0 = cadd(c0, c2), _e1 = csub(c0, c2);                \
    float2 _o0 = cadd(c1, c3), _o1 = cmulni(csub(c1, c3));        \
    d0 = cadd(_e0, _o0); d1 = cadd(_e1, _o1);                     \
    d2 = csub(_e0, _o0); d3 = csub(_e1, _o1);                     \
} while (0)

// ---------- shared passes (swzc addressing) ----------
__device__ __forceinline__ float2 h2f(__half2 v){ return __half22float2(v); }
__device__ __forceinline__ __half2 f2h(float2 v){ return __floats2half2_rn(v.x, v.y); }

// dense radix-16 first pass (M=1): B[16t+k] = DFT16(a)[k] * W128^{t k}
__device__ __forceinline__ void pass16f(const float2* __restrict__ A, float2* __restrict__ B,
                                        int rows, const float2* __restrict__ tw, int tid, int nth) {
    int total = rows << 3;
    for (int idx = tid; idx < total; idx += nth) {
        int r = idx >> 3, t = idx & 7;
        int base = r << 7;
        float2 ae[8], ao[8], E[8], O[8];
        #pragma unroll
        for (int m = 0; m < 8; m++) {
            ae[m] = A[base + swzc(r, t + 16 * m)];
            ao[m] = A[base + swzc(r, t + 8 + 16 * m)];
        }
        dft8(ae, E);
        dft8(ao, O);
        #pragma unroll
        for (int k = 0; k < 8; k++) {
            float2 wo = cmul(O[k], tw[(8 * k) & 127]);
            float2 c0 = cadd(E[k], wo);
            float2 c1 = csub(E[k], wo);
            B[base + swzc(r, 16 * t + k)]     = cmul(c0, tw[(t * k) & 127]);
            B[base + swzc(r, 16 * t + k + 8)] = cmul(c1, tw[(t * (k + 8)) & 127]);
        }
    }
}

// sparse radix-16 first pass (only inputs 0..31 nonzero) — fp32 / fp16 variants
__device__ __forceinline__ void pass16f_sp4(const float2* __restrict__ A, float2* __restrict__ B,
                                            int rows, const float2* __restrict__ tw, int tid, int nth) {
    int total = rows << 3;
    for (int idx = tid; idx < total; idx += nth) {
        int r = idx >> 3, t = idx & 7;
        int base = r << 7;
        float2 b0 = A[base + swzc(r, t)];
        float2 b1 = A[base + swzc(r, t + 8)];
        float2 b2 = A[base + swzc(r, t + 16)];
        float2 b3 = A[base + swzc(r, t + 24)];
        #pragma unroll
        for (int m = 0; m < 4; m++) {
            float2 c1 = cmul(b1, tw[(8  * m) & 127]);
            float2 c2 = cmul(b2, tw[(16 * m) & 127]);
            float2 c3 = cmul(b3, tw[(24 * m) & 127]);
            float2 d0, d1, d2, d3;
            DFT4_CORE(b0, c1, c2, c3, d0, d1, d2, d3);
            B[base + swzc(r, 16*t + m)]      = cmul(d0, tw[(t * (m))      & 127]);
            B[base + swzc(r, 16*t + m + 4)]  = cmul(d1, tw[(t * (m + 4))  & 127]);
            B[base + swzc(r, 16*t + m + 8)]  = cmul(d2, tw[(t * (m + 8))  & 127]);
            B[base + swzc(r, 16*t + m + 12)] = cmul(d3, tw[(t * (m + 12)) & 127]);
        }
    }
}

__device__ __forceinline__ void pass16h_sp4(const __half2* __restrict__ A, __half2* __restrict__ B,
                                            int rows, const float2* __restrict__ tw, int tid, int nth) {
    int total = rows << 3;
    for (int idx = tid; idx < total; idx += nth) {
        int r = idx >> 3, t = idx & 7;
        int base = r << 7;
        float2 b0 = h2f(A[base + swzc(r, t)]);
        float2 b1 = h2f(A[base + swzc(r, t + 8)]);
        float2 b2 = h2f(A[base + swzc(r, t + 16)]);
        float2 b3 = h2f(A[base + swzc(r, t + 24)]);
        #pragma unroll
        for (int m = 0; m < 4; m++) {
            float2 c1 = cmul(b1, tw[(8  * m) & 127]);
            float2 c2 = cmul(b2, tw[(16 * m) & 127]);
            float2 c3 = cmul(b3, tw[(24 * m) & 127]);
            float2 d0, d1, d2, d3;
            DFT4_CORE(b0, c1, c2, c3, d0, d1, d2, d3);
            B[base + swzc(r, 16*t + m)]      = f2h(cmul(d0, tw[(t * (m))      & 127]));
            B[base + swzc(r, 16*t + m + 4)]  = f2h(cmul(d1, tw[(t * (m + 4))  & 127]));
            B[base + swzc(r, 16*t + m + 8)]  = f2h(cmul(d2, tw[(t * (m + 8))  & 127]));
            B[base + swzc(r, 16*t + m + 12)] = f2h(cmul(d3, tw[(t * (m + 12)) & 127]));
        }
    }
}

// final radix-8 pass (M=16), hi==0 -> no twiddle
__device__ __forceinline__ void pass8f_nt(const float2* __restrict__ A, float2* __restrict__ B,
                                          int rows, int tid, int nth) {
    int total = rows << 4;
    for (int idx = tid; idx < total; idx += nth) {
        int r = idx >> 4, t = idx & 15;
        int base = r << 7;
        float2 a[8], c[8];
        #pragma unroll
        for (int j = 0; j < 8; j++) a[j] = A[base + swzc(r, t + 16 * j)];
        dft8(a, c);
        #pragma unroll
        for (int k = 0; k < 8; k++)
            B[base + swzc(r, t + 16 * k)] = c[k];
    }
}

__device__ __forceinline__ void pass8h_nt(const __half2* __restrict__ A, __half2* __restrict__ B,
                                          int rows, int tid, int nth) {
    int total = rows << 4;
    for (int idx = tid; idx < total; idx += nth) {
        int r = idx >> 4, t = idx & 15;
        int base = r << 7;
        float2 a[8], c[8];
        #pragma unroll
        for (int j = 0; j < 8; j++) a[j] = h2f(A[base + swzc(r, t + 16 * j)]);
        dft8(a, c);
        #pragma unroll
        for (int k = 0; k < 8; k++)
            B[base + swzc(r, t + 16 * k)] = f2h(c[k]);
    }
}

// 2-pass 128-pt FFT: A -> B -> A ; result in A
__device__ __forceinline__ float2* fft128_r16(float2* A, float2* B, int rows,
                                              const float2* tw, int tid, int nth) {
    pass16f(A, B, rows, tw, tid, nth); __syncthreads();
    pass8f_nt(B, A, rows, tid, nth);   __syncthreads();
    return A;
}

// ---------------- K1: 2D rFFT of x -> g_xf[bc][bin] ----------------
__global__ void __launch_bounds__(512) k_fft_x(const float* __restrict__ x) {
    extern __shared__ float2 sm[];
    float2* tw = sm;
    float2* bufA = sm + 128;
    float2* bufB = bufA + NBIN;
    int tid = threadIdx.x, nth = blockDim.x;
    int bc = blockIdx.x;

    make_twiddles(tw, tid);
    const float* img = x + (size_t)bc * HH * WW;
    for (int idx = tid; idx < 64 * 128; idx += nth) {
        int r = idx >> 7, n = idx & 127;
        bufA[(r << 7) + swzc(r, n)] = make_float2(img[(2 * r) * WW + n],
                                                  img[(2 * r + 1) * WW + n]);
    }
    __syncthreads();
    float2* P = fft128_r16(bufA, bufB, 64, tw, tid, nth);   // result in bufA
    for (int idx = tid; idx < 64 * NF; idx += nth) {
        int r = idx / NF, k = idx - r * NF;
        float2 Zk = P[(r << 7) + swzc(r, k)];
        float2 Zn = P[(r << 7) + swzc(r, (128 - k) & 127)];
        float2 Ar = make_float2(0.5f * (Zk.x + Zn.x), 0.5f * (Zk.y - Zn.y));
        float2 Br = make_float2(0.5f * (Zk.y + Zn.y), 0.5f * (Zn.x - Zk.x));
        bufB[(k << 7) + swzc(k, 2 * r)]     = Ar;
        bufB[(k << 7) + swzc(k, 2 * r + 1)] = Br;
    }
    __syncthreads();
    float2* Ff = fft128_r16(bufB, bufA, NF, tw, tid, nth);  // result in bufB
    float2* ob = g_xf + (size_t)bc * NBIN;
    for (int bin = tid; bin < NBIN; bin += nth) {
        int h = bin & 127;
        ob[bin] = Ff[(bin - h) + swzc(bin >> 7, h)];        // bin = k*128+h
    }
}

// ---------------- K2: 2D rFFT of filters (plain, fp16) -> g_kfn[c*F+f][bin] ----------------
#define SMEM_K2 (1024 + 2 * NBIN * 4)    // 67,584 B
__global__ void __launch_bounds__(512, 2) k_fft_k(const float* __restrict__ filt) {
    extern __shared__ char smk[];
    float2*  tw = (float2*)smk;
    __half2* CA = (__half2*)(smk + 1024);
    __half2* CB = (__half2*)(smk + 1024 + NBIN * 4);
    float2*  RA = (float2*)CB;                              // 16 KB
    float2*  RB = (float2*)(smk + 1024 + NBIN * 4 + 16384); // 16 KB (inside CB region)
    int tid = threadIdx.x, nth = blockDim.x;
    int fc = blockIdx.x;   // f*C + c (natural input order)
    int f = fc >> 7, c = fc & 127;

    make_twiddles(tw, tid);
    for (int idx = tid; idx < 16 * 128; idx += nth)
        RA[idx] = make_float2(0.f, 0.f);
    __syncthreads();
    const float* kimg = filt + (size_t)fc * KHH * KWW;
    for (int idx = tid; idx < KHH * KWW; idx += nth) {
        int i = idx / KWW, j = idx - i * KWW;
        float v = kimg[idx];
        int r = i >> 1;
        if (i & 1) RA[(r << 7) + swzc(r, j)].y = v;
        else       RA[(r << 7) + swzc(r, j)].x = v;
    }
    __syncthreads();
    pass16f_sp4(RA, RB, 16, tw, tid, nth); __syncthreads();
    pass8f_nt(RB, RA, 16, tid, nth);       __syncthreads();
    for (int idx = tid; idx < 16 * NF; idx += nth) {
        int r = idx / NF, k = idx - r * NF;
        float2 Zk = RA[(r << 7) + swzc(r, k)];
        float2 Zn = RA[(r << 7) + swzc(r, (128 - k) & 127)];
        float2 Ar = make_float2(0.5f * (Zk.x + Zn.x), 0.5f * (Zk.y - Zn.y));
        float2 Br = make_float2(0.5f * (Zk.y + Zn.y), 0.5f * (Zn.x - Zk.x));
        CA[(k << 7) + swzc(k, 2 * r)]     = f2h(Ar);
        CA[(k << 7) + swzc(k, 2 * r + 1)] = f2h(Br);
    }
    __syncthreads();
    pass16h_sp4(CA, CB, NF, tw, tid, nth); __syncthreads();
    pass8h_nt(CB, CA, NF, tid, nth);       __syncthreads();
    __half2* ob = g_kfn + (size_t)(c * F + f) * NBIN;
    for (int bin = tid; bin < NBIN; bin += nth) {
        int h = bin & 127;
        ob[bin] = CA[(bin - h) + swzc(bin >> 7, h)];
    }
}

// ---------------- K4: 4-bin complex GEMM, retiled 4b x 2f per thread ----------------
// CTA: 4 bins x 16 b x 128 f, K=128 c, 512 threads, 8 stages of 16 c.
// warp: binq = wid & 1, fg = (wid >> 1) & 1, b0 = (wid >> 2) * 4 (4 batches);
//       f = lane + 32 * (2*fg + j), j in {0,1}.
// accRE += Xr*Pp + Xi*Qq ; accIM += Xi*Pp + Xr*Qm  (Qm = -Qq)
//   per bin: re = Xr*p + Xi*q , im = Xi*p - Xr*q  ==  X * conj(K)  ✓
#define NB4 4
#define K4_CH 16
#define K4_XS_IM_OFF 32768
#define K4_KS_OFF    65536
#define K4_KSBUF_W   12288        // words per buffer (16c * 128f * 6)
#define SMEM_K4 (65536 + 2 * 49152)   // 163,840 B

__global__ void __launch_bounds__(512, 1) k_gemm4() {
    extern __shared__ char s4[];
    float* xre = (float*)s4;                      // [bc][4 bins]
    float* xim = (float*)(s4 + K4_XS_IM_OFF);
    float* ksf = (float*)(s4 + K4_KS_OFF);
    uint32_t ksb = smem_u32(s4 + K4_KS_OFF);
    int tid = threadIdx.x, lane = tid & 31, wid = tid >> 5;
    int bin0 = blockIdx.x * NB4;
    int binq = wid & 1;            // bin pair: bins bin0+2binq, +1
    int fg   = (wid >> 1) & 1;     // f half: f = lane + 32*(2*fg + j)
    int b0   = (wid >> 2) * 4;     // 4 batches

    #pragma unroll
    for (int m = 0; m < 8; m++) {
        int t = m * 512 + tid;
        int bc = t >> 1, quad = t & 1;
        float4 v = *(const float4*)&g_xf[(size_t)bc * NBIN + bin0 + 2 * quad];
        int w = bc * 4 + 2 * quad;
        *(float2*)&xre[w] = make_float2(v.x, v.z);
        *(float2*)&xim[w] = make_float2(v.y, v.w);
    }
    #pragma unroll
    for (int s = 0; s < 2; s++) {
        #pragma unroll
        for (int r = 0; r < 8; r++) {
            int m = r * 512 + tid;
            int cf = m >> 1, q = m & 1;
            int cc = cf >> 7, f = cf & 127;
            uint32_t dst = ksb + (uint32_t)(s * K4_KSBUF_W + (cc * 128 + f) * 6 + q * 2) * 4;
            const void* src = g_kfn + (size_t)((s * K4_CH + cc) * 128 + f) * NBIN + bin0 + q * 2;
            cp8(dst, src);
        }
        asm volatile("cp.async.commit_group;");
    }
    __syncthreads();

    unsigned long long accRE[8], accIM[8];   // [i*2 + j], i<4 batches, j<2 f's
    #pragma unroll
    for (int i = 0; i < 8; i++) { accRE[i] = 0ULL; accIM[i] = 0ULL; }

    #pragma unroll 1
    for (int s = 0; s < 8; s++) {
        if (s < 7) asm volatile("cp.async.wait_group 1;");
        else       asm volatile("cp.async.wait_group 0;");
        __syncthreads();
        int kbase = (s & 1) * K4_KSBUF_W;
        #pragma unroll
        for (int cc = 0; cc < K4_CH; cc++) {
            int c = s * K4_CH + cc;
            unsigned long long Pp[2], Qq[2], Qm[2];
            #pragma unroll
            for (int j = 0; j < 2; j++) {
                int f = lane + 32 * (2 * fg + j);
                int w = kbase + (cc * 128 + f) * 6 + 2 * binq;
                uint2 kk = *(const uint2*)&ksf[w];
                float2 kA = h2f(*reinterpret_cast<__half2*>(&kk.x));
                float2 kB = h2f(*reinterpret_cast<__half2*>(&kk.y));
                float nqA = -kA.y, nqB = -kB.y;
                asm("mov.b64 %0, {%1,%2};" : "=l"(Pp[j]) : "f"(kA.x), "f"(kB.x));
                asm("mov.b64 %0, {%1,%2};" : "=l"(Qq[j]) : "f"(kA.y), "f"(kB.y));
                asm("mov.b64 %0, {%1,%2};" : "=l"(Qm[j]) : "f"(nqA),  "f"(nqB));
            }
            #pragma unroll
            for (int i = 0; i < 4; i++) {
                int wx = ((b0 + i) * 128 + c) * 4 + 2 * binq;
                unsigned long long Xr = *(const unsigned long long*)&xre[wx];
                unsigned long long Xi = *(const unsigned long long*)&xim[wx];
                #pragma unroll
                for (int j = 0; j < 2; j++) {
                    asm("fma.rn.f32x2 %0, %1, %2, %0;" : "+l"(accRE[i * 2 + j]) : "l"(Xr), "l"(Pp[j]));
                    asm("fma.rn.f32x2 %0, %1, %2, %0;" : "+l"(accRE[i * 2 + j]) : "l"(Xi), "l"(Qq[j]));
                    asm("fma.rn.f32x2 %0, %1, %2, %0;" : "+l"(accIM[i * 2 + j]) : "l"(Xi), "l"(Pp[j]));
                    asm("fma.rn.f32x2 %0, %1, %2, %0;" : "+l"(accIM[i * 2 + j]) : "l"(Xr), "l"(Qm[j]));
                }
            }
        }
        __syncthreads();
        if (s < 6) {
            #pragma unroll
            for (int r = 0; r < 8; r++) {
                int m = r * 512 + tid;
                int cf = m >> 1, q = m & 1;
                int cc = cf >> 7, f = cf & 127;
                uint32_t dst = ksb + (uint32_t)((s & 1) * K4_KSBUF_W + (cc * 128 + f) * 6 + q * 2) * 4;
                const void* src = g_kfn + (size_t)(((s + 2) * K4_CH + cc) * 128 + f) * NBIN + bin0 + q * 2;
                cp8(dst, src);
            }
        }
        asm volatile("cp.async.commit_group;");
    }

    #pragma unroll
    for (int i = 0; i < 4; i++) {
        #pragma unroll
        for (int j = 0; j < 2; j++) {
            float2 re, im;
            asm("mov.b64 {%0,%1}, %2;" : "=f"(re.x), "=f"(re.y) : "l"(accRE[i * 2 + j]));
            asm("mov.b64 {%0,%1}, %2;" : "=f"(im.x), "=f"(im.y) : "l"(accIM[i * 2 + j]));
            int bf = (b0 + i) * 128 + lane + 32 * (2 * fg + j);
            *(float4*)&g_xf[(size_t)bf * NBIN + bin0 + 2 * binq] =
                make_float4(re.x, im.x, re.y, im.y);
        }
    }
}

// ---------------- K5: 2D irFFT + slice + bias (reads of^T from g_xf) ----------------
__global__ void __launch_bounds__(512) k_ifft(float* __restrict__ out,
                                              const float* __restrict__ bias) {
    extern __shared__ float2 sm[];
    float2* tw = sm;
    float2* bufA = sm + 128;
    float2* bufB = bufA + NBIN;
    int tid = threadIdx.x, nth = blockDim.x;
    int bf = blockIdx.x;
    int f  = bf & 127;

    make_twiddles(tw, tid);
    const float2* src = g_xf + (size_t)bf * NBIN;    // of^T row, coalesced
    for (int bin = tid; bin < NBIN; bin += nth) {
        float2 v = src[bin];
        int h = bin & 127;
        bufA[(bin - h) + swzc(bin >> 7, h)] = make_float2(v.x, -v.y);
    }
    __syncthreads();
    float2* R = fft128_r16(bufA, bufB, NF, tw, tid, nth);   // result in bufA
    for (int idx = tid; idx < 64 * 128; idx += nth) {
        int r = idx >> 7, kcol = idx & 127;
        float2 val;
        if (kcol <= 64) {
            float2 a = R[(kcol << 7) + swzc(kcol, 2 * r)];
            float2 b = R[(kcol << 7) + swzc(kcol, 2 * r + 1)];
            val = make_float2(a.x + b.y, a.y - b.x);
        } else {
            int kk = 128 - kcol;
            float2 a = R[(kk << 7) + swzc(kk, 2 * r)];
            float2 b = R[(kk << 7) + swzc(kk, 2 * r + 1)];
            val = make_float2(a.x - b.y, -a.y - b.x);
        }
        bufB[(r << 7) + swzc(r, kcol)] = val;
    }
    __syncthreads();
    float2* Y = fft128_r16(bufB, bufA, 64, tw, tid, nth);   // result in bufB
    const float inv = 1.0f / 16384.0f;
    float bv = bias[f];
    float* ob = out + (size_t)bf * OH * OW;
    for (int idx = tid; idx < OH * OW; idx += nth) {
        int oh = idx / OW, ow = idx - oh * OW;
        int r = oh >> 1;
        float2 y = Y[(r << 7) + swzc(r, ow)];
        float v = (oh & 1) ? -y.y : y.x;
        ob[idx] = v * inv + bv;
    }
}

// ---------------- launch ----------------
extern "C" void kernel_launch(void* const* d_in, const int* in_sizes, int n_in,
                              void* d_out, int out_size) {
    const float* x    = (const float*)d_in[0];
    const float* filt = (const float*)d_in[1];
    const float* bias = (const float*)d_in[2];
    float* out = (float*)d_out;

    int smFFT = (128 + 2 * NBIN) * (int)sizeof(float2);   // 134,144 B
    cudaFuncSetAttribute(k_fft_x, cudaFuncAttributeMaxDynamicSharedMemorySize, smFFT);
    cudaFuncSetAttribute(k_fft_k, cudaFuncAttributeMaxDynamicSharedMemorySize, SMEM_K2);
    cudaFuncSetAttribute(k_ifft,  cudaFuncAttributeMaxDynamicSharedMemorySize, smFFT);
    cudaFuncSetAttribute(k_gemm4, cudaFuncAttributeMaxDynamicSharedMemorySize, SMEM_K4);

    k_fft_x<<<BC, 512, smFFT>>>(x);
    k_fft_k<<<FC, 512, SMEM_K2>>>(filt);
    k_gemm4<<<NBIN / NB4, 512, SMEM_K4>>>();
    k_ifft<<<BC, 512, smFFT>>>(out, bias);
}

// round 17
// speedup vs baseline: 1.4272x; 1.0692x over previous
#include <cuda_runtime.h>
#include <cuda_fp16.h>
#include <cstdint>
#include <math.h>

#define BB 16
#define C  128
#define F  128
#define HH 128
#define WW 128
#define KHH 31
#define KWW 31
#define OH 98
#define OW 98
#define NF 65          // rfft bins along W
#define NBIN (HH*NF)   // 8320 ; bin = k*128 + h  (k-major)
#define BC (BB*C)      // 2048
#define FC (F*C)       // 16384

// -------- scratch (device globals; no allocation allowed) --------
__device__ float2  g_xf [(size_t)BC  * NBIN];   // [b*C+c][bin]; K4 overwrites in place with of^T [b*F+f][bin]
__device__ __half2 g_kfn[(size_t)FC  * NBIN];   // [c*F+f][bin]  (plain fft, fp16)

// ---------------- helpers ----------------
__device__ __forceinline__ int swzc(int r, int w) {
    int v = w ^ ((r & 3) << 3);
    return v ^ ((v >> 4) & 7);
}
__device__ __forceinline__ float2 cadd(float2 a, float2 b){return make_float2(a.x+b.x, a.y+b.y);}
__device__ __forceinline__ float2 csub(float2 a, float2 b){return make_float2(a.x-b.x, a.y-b.y);}
__device__ __forceinline__ float2 cmul(float2 a, float2 b){return make_float2(a.x*b.x-a.y*b.y, a.x*b.y+a.y*b.x);}
__device__ __forceinline__ float2 cmulni(float2 a){return make_float2(a.y, -a.x);}  // a * (-i)

__device__ __forceinline__ float2 h2f(__half2 v){ return __half22float2(v); }
__device__ __forceinline__ __half2 f2h(float2 v){ return __floats2half2_rn(v.x, v.y); }
// typed complex load/store (fp32 or fp16 storage, fp32 compute)
__device__ __forceinline__ float2 ldc(const float2* p){ return *p; }
__device__ __forceinline__ float2 ldc(const __half2* p){ return h2f(*p); }
__device__ __forceinline__ void stc(float2* p, float2 v){ *p = v; }
__device__ __forceinline__ void stc(__half2* p, float2 v){ *p = f2h(v); }

__device__ __forceinline__ void make_twiddles(float2* tw, int tid) {
    if (tid < 128) {
        float s, c;
        sincosf(-6.283185307179586f * (float)tid / 128.0f, &s, &c);
        tw[tid] = make_float2(c, s);
    }
}

__device__ __forceinline__ uint32_t smem_u32(const void* p) {
    uint32_t a;
    asm("{ .reg .u64 t; cvta.to.shared.u64 t, %1; cvt.u32.u64 %0, t; }" : "=r"(a) : "l"(p));
    return a;
}
__device__ __forceinline__ void cp8(uint32_t dst, const void* src) {
    asm volatile("cp.async.ca.shared.global [%0], [%1], 8;" :: "r"(dst), "l"(src));
}

// DFT8 natural order: c[k] = sum_j a[j] W8^{jk}
__device__ __forceinline__ void dft8(const float2* a, float2* c) {
    float2 t0 = cadd(a[0], a[4]), t1 = csub(a[0], a[4]);
    float2 t2 = cadd(a[2], a[6]), t3 = csub(a[2], a[6]);
    float2 m3 = cmulni(t3);
    float2 E0 = cadd(t0, t2), E2 = csub(t0, t2);
    float2 E1 = cadd(t1, m3), E3 = csub(t1, m3);
    t0 = cadd(a[1], a[5]); t1 = csub(a[1], a[5]);
    t2 = cadd(a[3], a[7]); t3 = csub(a[3], a[7]);
    m3 = cmulni(t3);
    float2 O0 = cadd(t0, t2), O2 = csub(t0, t2);
    float2 O1 = cadd(t1, m3), O3 = csub(t1, m3);
    const float s = 0.70710678118654752f;
    float2 w1o = make_float2(s * (O1.x + O1.y), s * (O1.y - O1.x));
    float2 w2o = cmulni(O2);
    float2 w3o = make_float2(s * (O3.y - O3.x), s * (-O3.x - O3.y));
    c[0] = cadd(E0, O0);  c[4] = csub(E0, O0);
    c[1] = cadd(E1, w1o); c[5] = csub(E1, w1o);
    c[2] = cadd(E2, w2o); c[6] = csub(E2, w2o);
    c[3] = cadd(E3, w3o); c[7] = csub(E3, w3o);
}

#define DFT4_CORE(c0, c1, c2, c3, d0, d1, d2, d3) do {            \
    float2 _e0 = cadd(c0, c2), _e1 = csub(c0, c2);                \
    float2 _o0 = cadd(c1, c3), _o1 = cmulni(csub(c1, c3));        \
    d0 = cadd(_e0, _o0); d1 = cadd(_e1, _o1);                     \
    d2 = csub(_e0, _o0); d3 = csub(_e1, _o1);                     \
} while (0)

// ---------- templated Stockham passes (swzc addressing, fp32 compute) ----------
// dense radix-16 first pass (M=1): B[16t+k] = DFT16(a)[k] * W128^{t k}
template<typename TA, typename TB>
__device__ __forceinline__ void pass16t(const TA* __restrict__ A, TB* __restrict__ B,
                                        int rows, const float2* __restrict__ tw, int tid, int nth) {
    int total = rows << 3;
    for (int idx = tid; idx < total; idx += nth) {
        int r = idx >> 3, t = idx & 7;
        int base = r << 7;
        float2 ae[8], ao[8], E[8], O[8];
        #pragma unroll
        for (int m = 0; m < 8; m++) {
            ae[m] = ldc(&A[base + swzc(r, t + 16 * m)]);
            ao[m] = ldc(&A[base + swzc(r, t + 8 + 16 * m)]);
        }
        dft8(ae, E);
        dft8(ao, O);
        #pragma unroll
        for (int k = 0; k < 8; k++) {
            float2 wo = cmul(O[k], tw[(8 * k) & 127]);
            float2 c0 = cadd(E[k], wo);
            float2 c1 = csub(E[k], wo);
            stc(&B[base + swzc(r, 16 * t + k)],     cmul(c0, tw[(t * k) & 127]));
            stc(&B[base + swzc(r, 16 * t + k + 8)], cmul(c1, tw[(t * (k + 8)) & 127]));
        }
    }
}

// sparse radix-16 first pass (only inputs 0..31 nonzero)
template<typename TA, typename TB>
__device__ __forceinline__ void pass16t_sp4(const TA* __restrict__ A, TB* __restrict__ B,
                                            int rows, const float2* __restrict__ tw, int tid, int nth) {
    int total = rows << 3;
    for (int idx = tid; idx < total; idx += nth) {
        int r = idx >> 3, t = idx & 7;
        int base = r << 7;
        float2 b0 = ldc(&A[base + swzc(r, t)]);
        float2 b1 = ldc(&A[base + swzc(r, t + 8)]);
        float2 b2 = ldc(&A[base + swzc(r, t + 16)]);
        float2 b3 = ldc(&A[base + swzc(r, t + 24)]);
        #pragma unroll
        for (int m = 0; m < 4; m++) {
            float2 c1 = cmul(b1, tw[(8  * m) & 127]);
            float2 c2 = cmul(b2, tw[(16 * m) & 127]);
            float2 c3 = cmul(b3, tw[(24 * m) & 127]);
            float2 d0, d1, d2, d3;
            DFT4_CORE(b0, c1, c2, c3, d0, d1, d2, d3);
            stc(&B[base + swzc(r, 16*t + m)],      cmul(d0, tw[(t * (m))      & 127]));
            stc(&B[base + swzc(r, 16*t + m + 4)],  cmul(d1, tw[(t * (m + 4))  & 127]));
            stc(&B[base + swzc(r, 16*t + m + 8)],  cmul(d2, tw[(t * (m + 8))  & 127]));
            stc(&B[base + swzc(r, 16*t + m + 12)], cmul(d3, tw[(t * (m + 12)) & 127]));
        }
    }
}

// final radix-8 pass (M=16), hi==0 -> no twiddle
template<typename TA, typename TB>
__device__ __forceinline__ void pass8t_nt(const TA* __restrict__ A, TB* __restrict__ B,
                                          int rows, int tid, int nth) {
    int total = rows << 4;
    for (int idx = tid; idx < total; idx += nth) {
        int r = idx >> 4, t = idx & 15;
        int base = r << 7;
        float2 a[8], c[8];
        #pragma unroll
        for (int j = 0; j < 8; j++) a[j] = ldc(&A[base + swzc(r, t + 16 * j)]);
        dft8(a, c);
        #pragma unroll
        for (int k = 0; k < 8; k++)
            stc(&B[base + swzc(r, t + 16 * k)], c[k]);
    }
}

// mixed 2-pass 128-pt FFT: A(f32) -> B(f16) -> A(f32); result in A
__device__ __forceinline__ void fft128_mix(float2* A, __half2* B, int rows,
                                           const float2* tw, int tid, int nth) {
    pass16t(A, B, rows, tw, tid, nth); __syncthreads();
    pass8t_nt(B, A, rows, tid, nth);   __syncthreads();
}

// ---------------- K1: 2D rFFT of x -> g_xf[bc][bin] ----------------
// smem: tw 1KB | A f32 (66,560) | B f16 (33,280) = 100,864 -> 2 CTAs/SM
#define SMEM_FFT2 (1024 + NBIN * 8 + NBIN * 4)
__global__ void __launch_bounds__(512, 2) k_fft_x(const float* __restrict__ x) {
    extern __shared__ char smr[];
    float2*  tw = (float2*)smr;
    float2*  A  = (float2*)(smr + 1024);
    __half2* B  = (__half2*)(smr + 1024 + NBIN * 8);
    int tid = threadIdx.x, nth = blockDim.x;
    int bc = blockIdx.x;

    make_twiddles(tw, tid);
    const float* img = x + (size_t)bc * HH * WW;
    for (int idx = tid; idx < 64 * 128; idx += nth) {
        int r = idx >> 7, n = idx & 127;
        A[(r << 7) + swzc(r, n)] = make_float2(img[(2 * r) * WW + n],
                                               img[(2 * r + 1) * WW + n]);
    }
    __syncthreads();
    fft128_mix(A, B, 64, tw, tid, nth);          // row FFT, result in A
    // unpack rfft rows -> B[k][h'] (fp16, 65 rows)
    for (int idx = tid; idx < 64 * NF; idx += nth) {
        int r = idx / NF, k = idx - r * NF;
        float2 Zk = A[(r << 7) + swzc(r, k)];
        float2 Zn = A[(r << 7) + swzc(r, (128 - k) & 127)];
        float2 Ar = make_float2(0.5f * (Zk.x + Zn.x), 0.5f * (Zk.y - Zn.y));
        float2 Br = make_float2(0.5f * (Zk.y + Zn.y), 0.5f * (Zn.x - Zk.x));
        B[(k << 7) + swzc(k, 2 * r)]     = f2h(Ar);
        B[(k << 7) + swzc(k, 2 * r + 1)] = f2h(Br);
    }
    __syncthreads();
    // col FFT: B(f16) -> A(f32) -> B(f16); result in B
    pass16t(B, A, NF, tw, tid, nth); __syncthreads();
    pass8t_nt(A, B, NF, tid, nth);   __syncthreads();
    float2* ob = g_xf + (size_t)bc * NBIN;
    for (int bin = tid; bin < NBIN; bin += nth) {
        int h = bin & 127;
        ob[bin] = h2f(B[(bin - h) + swzc(bin >> 7, h)]);   // bin = k*128+h
    }
}

// ---------------- K2: 2D rFFT of filters (plain, fp16) -> g_kfn[c*F+f][bin] ----------------
#define SMEM_K2 (1024 + 2 * NBIN * 4)    // 67,584 B
__global__ void __launch_bounds__(512, 2) k_fft_k(const float* __restrict__ filt) {
    extern __shared__ char smk[];
    float2*  tw = (float2*)smk;
    __half2* CA = (__half2*)(smk + 1024);
    __half2* CB = (__half2*)(smk + 1024 + NBIN * 4);
    float2*  RA = (float2*)CB;                              // 16 KB
    float2*  RB = (float2*)(smk + 1024 + NBIN * 4 + 16384); // 16 KB (inside CB region)
    int tid = threadIdx.x, nth = blockDim.x;
    int fc = blockIdx.x;   // f*C + c (natural input order)
    int f = fc >> 7, c = fc & 127;

    make_twiddles(tw, tid);
    for (int idx = tid; idx < 16 * 128; idx += nth)
        RA[idx] = make_float2(0.f, 0.f);
    __syncthreads();
    const float* kimg = filt + (size_t)fc * KHH * KWW;
    for (int idx = tid; idx < KHH * KWW; idx += nth) {
        int i = idx / KWW, j = idx - i * KWW;
        float v = kimg[idx];
        int r = i >> 1;
        if (i & 1) RA[(r << 7) + swzc(r, j)].y = v;
        else       RA[(r << 7) + swzc(r, j)].x = v;
    }
    __syncthreads();
    pass16t_sp4(RA, RB, 16, tw, tid, nth); __syncthreads();
    pass8t_nt(RB, RA, 16, tid, nth);       __syncthreads();
    for (int idx = tid; idx < 16 * NF; idx += nth) {
        int r = idx / NF, k = idx - r * NF;
        float2 Zk = RA[(r << 7) + swzc(r, k)];
        float2 Zn = RA[(r << 7) + swzc(r, (128 - k) & 127)];
        float2 Ar = make_float2(0.5f * (Zk.x + Zn.x), 0.5f * (Zk.y - Zn.y));
        float2 Br = make_float2(0.5f * (Zk.y + Zn.y), 0.5f * (Zn.x - Zk.x));
        CA[(k << 7) + swzc(k, 2 * r)]     = f2h(Ar);
        CA[(k << 7) + swzc(k, 2 * r + 1)] = f2h(Br);
    }
    __syncthreads();
    pass16t_sp4(CA, CB, NF, tw, tid, nth); __syncthreads();
    pass8t_nt(CB, CA, NF, tid, nth);       __syncthreads();
    __half2* ob = g_kfn + (size_t)(c * F + f) * NBIN;
    for (int bin = tid; bin < NBIN; bin += nth) {
        int h = bin & 127;
        ob[bin] = CA[(bin - h) + swzc(bin >> 7, h)];
    }
}

// ---------------- K4: 4-bin complex GEMM, retiled 4b x 2f per thread (R16 proven) ----------------
#define NB4 4
#define K4_CH 16
#define K4_XS_IM_OFF 32768
#define K4_KS_OFF    65536
#define K4_KSBUF_W   12288        // words per buffer (16c * 128f * 6)
#define SMEM_K4 (65536 + 2 * 49152)   // 163,840 B

__global__ void __launch_bounds__(512, 1) k_gemm4() {
    extern __shared__ char s4[];
    float* xre = (float*)s4;                      // [bc][4 bins]
    float* xim = (float*)(s4 + K4_XS_IM_OFF);
    float* ksf = (float*)(s4 + K4_KS_OFF);
    uint32_t ksb = smem_u32(s4 + K4_KS_OFF);
    int tid = threadIdx.x, lane = tid & 31, wid = tid >> 5;
    int bin0 = blockIdx.x * NB4;
    int binq = wid & 1;            // bin pair: bins bin0+2binq, +1
    int fg   = (wid >> 1) & 1;     // f half: f = lane + 32*(2*fg + j)
    int b0   = (wid >> 2) * 4;     // 4 batches

    #pragma unroll
    for (int m = 0; m < 8; m++) {
        int t = m * 512 + tid;
        int bc = t >> 1, quad = t & 1;
        float4 v = *(const float4*)&g_xf[(size_t)bc * NBIN + bin0 + 2 * quad];
        int w = bc * 4 + 2 * quad;
        *(float2*)&xre[w] = make_float2(v.x, v.z);
        *(float2*)&xim[w] = make_float2(v.y, v.w);
    }
    #pragma unroll
    for (int s = 0; s < 2; s++) {
        #pragma unroll
        for (int r = 0; r < 8; r++) {
            int m = r * 512 + tid;
            int cf = m >> 1, q = m & 1;
            int cc = cf >> 7, f = cf & 127;
            uint32_t dst = ksb + (uint32_t)(s * K4_KSBUF_W + (cc * 128 + f) * 6 + q * 2) * 4;
            const void* src = g_kfn + (size_t)((s * K4_CH + cc) * 128 + f) * NBIN + bin0 + q * 2;
            cp8(dst, src);
        }
        asm volatile("cp.async.commit_group;");
    }
    __syncthreads();

    unsigned long long accRE[8], accIM[8];   // [i*2 + j], i<4 batches, j<2 f's
    #pragma unroll
    for (int i = 0; i < 8; i++) { accRE[i] = 0ULL; accIM[i] = 0ULL; }

    #pragma unroll 1
    for (int s = 0; s < 8; s++) {
        if (s < 7) asm volatile("cp.async.wait_group 1;");
        else       asm volatile("cp.async.wait_group 0;");
        __syncthreads();
        int kbase = (s & 1) * K4_KSBUF_W;
        #pragma unroll
        for (int cc = 0; cc < K4_CH; cc++) {
            int c = s * K4_CH + cc;
            unsigned long long Pp[2], Qq[2], Qm[2];
            #pragma unroll
            for (int j = 0; j < 2; j++) {
                int f = lane + 32 * (2 * fg + j);
                int w = kbase + (cc * 128 + f) * 6 + 2 * binq;
                uint2 kk = *(const uint2*)&ksf[w];
                float2 kA = h2f(*reinterpret_cast<__half2*>(&kk.x));
                float2 kB = h2f(*reinterpret_cast<__half2*>(&kk.y));
                float nqA = -kA.y, nqB = -kB.y;
                asm("mov.b64 %0, {%1,%2};" : "=l"(Pp[j]) : "f"(kA.x), "f"(kB.x));
                asm("mov.b64 %0, {%1,%2};" : "=l"(Qq[j]) : "f"(kA.y), "f"(kB.y));
                asm("mov.b64 %0, {%1,%2};" : "=l"(Qm[j]) : "f"(nqA),  "f"(nqB));
            }
            #pragma unroll
            for (int i = 0; i < 4; i++) {
                int wx = ((b0 + i) * 128 + c) * 4 + 2 * binq;
                unsigned long long Xr = *(const unsigned long long*)&xre[wx];
                unsigned long long Xi = *(const unsigned long long*)&xim[wx];
                #pragma unroll
                for (int j = 0; j < 2; j++) {
                    asm("fma.rn.f32x2 %0, %1, %2, %0;" : "+l"(accRE[i * 2 + j]) : "l"(Xr), "l"(Pp[j]));
                    asm("fma.rn.f32x2 %0, %1, %2, %0;" : "+l"(accRE[i * 2 + j]) : "l"(Xi), "l"(Qq[j]));
                    asm("fma.rn.f32x2 %0, %1, %2, %0;" : "+l"(accIM[i * 2 + j]) : "l"(Xi), "l"(Pp[j]));
                    asm("fma.rn.f32x2 %0, %1, %2, %0;" : "+l"(accIM[i * 2 + j]) : "l"(Xr), "l"(Qm[j]));
                }
            }
        }
        __syncthreads();
        if (s < 6) {
            #pragma unroll
            for (int r = 0; r < 8; r++) {
                int m = r * 512 + tid;
                int cf = m >> 1, q = m & 1;
                int cc = cf >> 7, f = cf & 127;
                uint32_t dst = ksb + (uint32_t)((s & 1) * K4_KSBUF_W + (cc * 128 + f) * 6 + q * 2) * 4;
                const void* src = g_kfn + (size_t)(((s + 2) * K4_CH + cc) * 128 + f) * NBIN + bin0 + q * 2;
                cp8(dst, src);
            }
        }
        asm volatile("cp.async.commit_group;");
    }

    #pragma unroll
    for (int i = 0; i < 4; i++) {
        #pragma unroll
        for (int j = 0; j < 2; j++) {
            float2 re, im;
            asm("mov.b64 {%0,%1}, %2;" : "=f"(re.x), "=f"(re.y) : "l"(accRE[i * 2 + j]));
            asm("mov.b64 {%0,%1}, %2;" : "=f"(im.x), "=f"(im.y) : "l"(accIM[i * 2 + j]));
            int bf = (b0 + i) * 128 + lane + 32 * (2 * fg + j);
            *(float4*)&g_xf[(size_t)bf * NBIN + bin0 + 2 * binq] =
                make_float4(re.x, im.x, re.y, im.y);
        }
    }
}

// ---------------- K5: 2D irFFT + slice + bias (reads of^T from g_xf) ----------------
__global__ void __launch_bounds__(512, 2) k_ifft(float* __restrict__ out,
                                                 const float* __restrict__ bias) {
    extern __shared__ char smr[];
    float2*  tw = (float2*)smr;
    float2*  A  = (float2*)(smr + 1024);
    __half2* B  = (__half2*)(smr + 1024 + NBIN * 8);
    int tid = threadIdx.x, nth = blockDim.x;
    int bf = blockIdx.x;
    int f  = bf & 127;

    make_twiddles(tw, tid);
    const float inv = 1.0f / 16384.0f;            // folded at load (fp16 overflow guard)
    const float2* src = g_xf + (size_t)bf * NBIN; // of^T row, coalesced
    for (int bin = tid; bin < NBIN; bin += nth) {
        float2 v = src[bin];
        int h = bin & 127;
        A[(bin - h) + swzc(bin >> 7, h)] = make_float2(v.x * inv, -v.y * inv);
    }
    __syncthreads();
    fft128_mix(A, B, NF, tw, tid, nth);           // col FFT, result in A
    // combine -> B rows r (fp16, 64 rows)
    for (int idx = tid; idx < 64 * 128; idx += nth) {
        int r = idx >> 7, kcol = idx & 127;
        float2 val;
        if (kcol <= 64) {
            float2 a = A[(kcol << 7) + swzc(kcol, 2 * r)];
            float2 b = A[(kcol << 7) + swzc(kcol, 2 * r + 1)];
            val = make_float2(a.x + b.y, a.y - b.x);
        } else {
            int kk = 128 - kcol;
            float2 a = A[(kk << 7) + swzc(kk, 2 * r)];
            float2 b = A[(kk << 7) + swzc(kk, 2 * r + 1)];
            val = make_float2(a.x - b.y, -a.y - b.x);
        }
        B[(r << 7) + swzc(r, kcol)] = f2h(val);
    }
    __syncthreads();
    // row FFT: B(f16) -> A(f32) -> B(f16); result in B
    pass16t(B, A, 64, tw, tid, nth); __syncthreads();
    pass8t_nt(A, B, 64, tid, nth);   __syncthreads();
    float bv = bias[f];
    float* ob = out + (size_t)bf * OH * OW;
    for (int idx = tid; idx < OH * OW; idx += nth) {
        int oh = idx / OW, ow = idx - oh * OW;
        int r = oh >> 1;
        float2 y = h2f(B[(r << 7) + swzc(r, ow)]);
        float v = (oh & 1) ? -y.y : y.x;
        ob[idx] = v + bv;
    }
}

// ---------------- launch ----------------
extern "C" void kernel_launch(void* const* d_in, const int* in_sizes, int n_in,
                              void* d_out, int out_size) {
    const float* x    = (const float*)d_in[0];
    const float* filt = (const float*)d_in[1];
    const float* bias = (const float*)d_in[2];
    float* out = (float*)d_out;

    cudaFuncSetAttribute(k_fft_x, cudaFuncAttributeMaxDynamicSharedMemorySize, SMEM_FFT2);
    cudaFuncSetAttribute(k_fft_k, cudaFuncAttributeMaxDynamicSharedMemorySize, SMEM_K2);
    cudaFuncSetAttribute(k_ifft,  cudaFuncAttributeMaxDynamicSharedMemorySize, SMEM_FFT2);
    cudaFuncSetAttribute(k_gemm4, cudaFuncAttributeMaxDynamicSharedMemorySize, SMEM_K4);

    k_fft_x<<<BC, 512, SMEM_FFT2>>>(x);
    k_fft_k<<<FC, 512, SMEM_K2>>>(filt);
    k_gemm4<<<NBIN / NB4, 512, SMEM_K4>>>();
    k_ifft<<<BC, 512, SMEM_FFT2>>>(out, bias);
}